// round 1
// baseline (speedup 1.0000x reference)
#include <cuda_runtime.h>
#include <math.h>

#define D_MODEL 1024
#define NH      16
#define HD      64
#define DFF     4096
#define SEQ     2048
#define BATCH   2
#define NTOK    (BATCH*SEQ)          // 4096
#define NEG_BIG (-1e30f)

// ---------------- scratch (allocation-free rule: __device__ globals) --------
__device__ float g_xn  [NTOK * D_MODEL];       // 16 MB  (LN output, reused for LN2)
__device__ float g_qkv [NTOK * 3 * D_MODEL];   // 48 MB
__device__ float g_ctx [NTOK * D_MODEL];       // 16 MB
__device__ float g_src2[NTOK * D_MODEL];       // 16 MB  (after attention residual)
__device__ float g_ff1 [NTOK * DFF];           // 64 MB

// ---------------- LayerNorm: one block per row ------------------------------
__global__ __launch_bounds__(256) void ln_kernel(
    const float* __restrict__ x, const float* __restrict__ w,
    const float* __restrict__ b, float* __restrict__ y)
{
    const int row = blockIdx.x;
    const int tid = threadIdx.x;
    const float* xr = x + (size_t)row * D_MODEL;

    float4 v = *(const float4*)&xr[tid * 4];
    float s  = v.x + v.y + v.z + v.w;
    float ss = v.x*v.x + v.y*v.y + v.z*v.z + v.w*v.w;
    #pragma unroll
    for (int o = 16; o > 0; o >>= 1) {
        s  += __shfl_xor_sync(0xffffffffu, s,  o);
        ss += __shfl_xor_sync(0xffffffffu, ss, o);
    }
    __shared__ float rs[8], rss[8];
    if ((tid & 31) == 0) { rs[tid >> 5] = s; rss[tid >> 5] = ss; }
    __syncthreads();
    float ts = 0.f, tss = 0.f;
    #pragma unroll
    for (int i = 0; i < 8; i++) { ts += rs[i]; tss += rss[i]; }

    const float mu  = ts * (1.0f / D_MODEL);
    const float var = fmaxf(tss * (1.0f / D_MODEL) - mu * mu, 0.0f);
    const float inv = rsqrtf(var + 1e-5f);

    float4 wv = *(const float4*)&w[tid * 4];
    float4 bv = *(const float4*)&b[tid * 4];
    float4 o;
    o.x = (v.x - mu) * inv * wv.x + bv.x;
    o.y = (v.y - mu) * inv * wv.y + bv.y;
    o.z = (v.z - mu) * inv * wv.z + bv.z;
    o.w = (v.w - mu) * inv * wv.w + bv.w;
    *(float4*)&(y + (size_t)row * D_MODEL)[tid * 4] = o;
}

// ---------------- Generic GEMM: C = A@B + bias (+ReLU) (+res) ---------------
// 128x128 block tile, BK=8, 256 threads, 8x8 micro-tile. M,N %128==0, K %8==0.
__global__ __launch_bounds__(256) void gemm_kernel(
    const float* __restrict__ A, const float* __restrict__ B,
    const float* __restrict__ bias, const float* __restrict__ res,
    float* __restrict__ C, int M, int N, int K, int relu)
{
    __shared__ float As[8][128];   // transposed: As[k][m]
    __shared__ float Bs[8][128];   // Bs[k][n]

    const int bm = blockIdx.y * 128;
    const int bn = blockIdx.x * 128;
    const int tid = threadIdx.x;
    const int tx = tid & 15, ty = tid >> 4;
    const int m0 = ty * 8, n0 = tx * 8;

    float acc[8][8];
    #pragma unroll
    for (int i = 0; i < 8; i++)
        #pragma unroll
        for (int j = 0; j < 8; j++) acc[i][j] = 0.f;

    const int arow = tid >> 1, ac = (tid & 1) * 4;
    const int brow = tid >> 5, bc = (tid & 31) * 4;
    const float* Aptr = A + (size_t)(bm + arow) * K + ac;
    const float* Bptr = B + (size_t)brow * N + bn + bc;

    for (int k0 = 0; k0 < K; k0 += 8) {
        float4 av = *(const float4*)(Aptr + k0);
        As[ac + 0][arow] = av.x; As[ac + 1][arow] = av.y;
        As[ac + 2][arow] = av.z; As[ac + 3][arow] = av.w;
        *(float4*)&Bs[brow][bc] = *(const float4*)(Bptr + (size_t)k0 * N);
        __syncthreads();

        #pragma unroll
        for (int k = 0; k < 8; k++) {
            float a[8], bb[8];
            *(float4*)&a[0]  = *(const float4*)&As[k][m0];
            *(float4*)&a[4]  = *(const float4*)&As[k][m0 + 4];
            *(float4*)&bb[0] = *(const float4*)&Bs[k][n0];
            *(float4*)&bb[4] = *(const float4*)&Bs[k][n0 + 4];
            #pragma unroll
            for (int i = 0; i < 8; i++)
                #pragma unroll
                for (int j = 0; j < 8; j++)
                    acc[i][j] = fmaf(a[i], bb[j], acc[i][j]);
        }
        __syncthreads();
    }

    #pragma unroll
    for (int i = 0; i < 8; i++) {
        const int m = bm + m0 + i;
        #pragma unroll
        for (int j4 = 0; j4 < 8; j4 += 4) {
            const int n = bn + n0 + j4;
            float4 o;
            o.x = acc[i][j4 + 0] + bias[n + 0];
            o.y = acc[i][j4 + 1] + bias[n + 1];
            o.z = acc[i][j4 + 2] + bias[n + 2];
            o.w = acc[i][j4 + 3] + bias[n + 3];
            if (relu) {
                o.x = fmaxf(o.x, 0.f); o.y = fmaxf(o.y, 0.f);
                o.z = fmaxf(o.z, 0.f); o.w = fmaxf(o.w, 0.f);
            }
            if (res) {
                float4 r = *(const float4*)&res[(size_t)m * N + n];
                o.x += r.x; o.y += r.y; o.z += r.z; o.w += r.w;
            }
            *(float4*)&C[(size_t)m * N + n] = o;
        }
    }
}

// ---------------- Flash attention with ALiBi + causal -----------------------
// Block = (q-tile of 64, head, batch). 256 threads, 4x4 micro-tiles.
// Dynamic smem: Qs/Ks (64x68, [d][r]), Vs (64x68, [k][c]), Ps (64x68, [k][r]).
#define ASTRIDE 68
#define ATTN_SMEM (4 * 64 * ASTRIDE * (int)sizeof(float))

__global__ __launch_bounds__(256) void attn_kernel(
    const float* __restrict__ qkv, float* __restrict__ ctx)
{
    extern __shared__ float sm[];
    float* Qs = sm;
    float* Ks = sm + 1 * 64 * ASTRIDE;
    float* Vs = sm + 2 * 64 * ASTRIDE;
    float* Ps = sm + 3 * 64 * ASTRIDE;

    const int qt = blockIdx.x, h = blockIdx.y, b = blockIdx.z;
    const int tid = threadIdx.x;
    const int tx = tid & 15, ty = tid >> 4;
    const int r0 = ty * 4, c0 = tx * 4;
    const int q_base = qt * 64;
    const size_t tok0 = (size_t)b * SEQ;
    const float scale = 0.125f;                 // 1/sqrt(64)
    const float slope = -exp2f(-(float)h);

    // load Q tile transposed: Qs[d][r]
    for (int i = tid; i < 64 * 16; i += 256) {
        const int r = i >> 4, d = (i & 15) * 4;
        float4 v = *(const float4*)&qkv[(tok0 + q_base + r) * 3072 + h * 64 + d];
        Qs[(d + 0) * ASTRIDE + r] = v.x; Qs[(d + 1) * ASTRIDE + r] = v.y;
        Qs[(d + 2) * ASTRIDE + r] = v.z; Qs[(d + 3) * ASTRIDE + r] = v.w;
    }

    float m_run[4], l_run[4], acc[4][4];
    #pragma unroll
    for (int i = 0; i < 4; i++) {
        m_run[i] = NEG_BIG; l_run[i] = 0.f;
        #pragma unroll
        for (int j = 0; j < 4; j++) acc[i][j] = 0.f;
    }
    __syncthreads();

    for (int kt = 0; kt <= qt; kt++) {
        const int k_base = kt * 64;
        // load K (transposed [d][j]) and V ([k][c])
        for (int i = tid; i < 64 * 16; i += 256) {
            const int j = i >> 4, d = (i & 15) * 4;
            const float* base = &qkv[(tok0 + k_base + j) * 3072 + h * 64 + d];
            float4 kv = *(const float4*)(base + 1024);
            Ks[(d + 0) * ASTRIDE + j] = kv.x; Ks[(d + 1) * ASTRIDE + j] = kv.y;
            Ks[(d + 2) * ASTRIDE + j] = kv.z; Ks[(d + 3) * ASTRIDE + j] = kv.w;
            *(float4*)&Vs[j * ASTRIDE + d] = *(const float4*)(base + 2048);
        }
        __syncthreads();

        // S = Q K^T  (4x4 per thread)
        float s[4][4];
        #pragma unroll
        for (int i = 0; i < 4; i++)
            #pragma unroll
            for (int j = 0; j < 4; j++) s[i][j] = 0.f;
        #pragma unroll 8
        for (int d = 0; d < 64; d++) {
            float4 qa = *(const float4*)&Qs[d * ASTRIDE + r0];
            float4 kb = *(const float4*)&Ks[d * ASTRIDE + c0];
            const float qv[4] = {qa.x, qa.y, qa.z, qa.w};
            const float kv[4] = {kb.x, kb.y, kb.z, kb.w};
            #pragma unroll
            for (int i = 0; i < 4; i++)
                #pragma unroll
                for (int j = 0; j < 4; j++)
                    s[i][j] = fmaf(qv[i], kv[j], s[i][j]);
        }

        const bool diag = (kt == qt);
        #pragma unroll
        for (int i = 0; i < 4; i++) {
            const int qi = q_base + r0 + i;
            float rowmax = NEG_BIG;
            #pragma unroll
            for (int j = 0; j < 4; j++) {
                const int kj = k_base + c0 + j;
                float v = fmaf(s[i][j], scale, (float)(qi + kj) * slope);
                if (diag && kj > qi) v = NEG_BIG;
                s[i][j] = v;
                rowmax = fmaxf(rowmax, v);
            }
            #pragma unroll
            for (int o = 1; o < 16; o <<= 1)
                rowmax = fmaxf(rowmax, __shfl_xor_sync(0xffffffffu, rowmax, o));
            const float m_new = fmaxf(m_run[i], rowmax);
            const float corr = __expf(m_run[i] - m_new);
            float ps = 0.f;
            #pragma unroll
            for (int j = 0; j < 4; j++) {
                const float p = __expf(s[i][j] - m_new);
                s[i][j] = p; ps += p;
            }
            #pragma unroll
            for (int o = 1; o < 16; o <<= 1)
                ps += __shfl_xor_sync(0xffffffffu, ps, o);
            l_run[i] = l_run[i] * corr + ps;
            m_run[i] = m_new;
            #pragma unroll
            for (int j = 0; j < 4; j++) acc[i][j] *= corr;
        }

        // stash P transposed [k][r] for the PV GEMM
        #pragma unroll
        for (int i = 0; i < 4; i++)
            #pragma unroll
            for (int j = 0; j < 4; j++)
                Ps[(c0 + j) * ASTRIDE + (r0 + i)] = s[i][j];
        __syncthreads();

        // O += P V
        #pragma unroll 8
        for (int k = 0; k < 64; k++) {
            float4 pa = *(const float4*)&Ps[k * ASTRIDE + r0];
            float4 vb = *(const float4*)&Vs[k * ASTRIDE + c0];
            const float pv[4] = {pa.x, pa.y, pa.z, pa.w};
            const float vv[4] = {vb.x, vb.y, vb.z, vb.w};
            #pragma unroll
            for (int i = 0; i < 4; i++)
                #pragma unroll
                for (int j = 0; j < 4; j++)
                    acc[i][j] = fmaf(pv[i], vv[j], acc[i][j]);
        }
        __syncthreads();
    }

    // normalize and write ctx in [b, s, h*64 + d] layout
    #pragma unroll
    for (int i = 0; i < 4; i++) {
        const float inv = 1.0f / l_run[i];
        float4 o = make_float4(acc[i][0] * inv, acc[i][1] * inv,
                               acc[i][2] * inv, acc[i][3] * inv);
        *(float4*)&ctx[(tok0 + q_base + r0 + i) * D_MODEL + h * 64 + c0] = o;
    }
}

// ---------------- launch ----------------------------------------------------
extern "C" void kernel_launch(void* const* d_in, const int* in_sizes, int n_in,
                              void* d_out, int out_size)
{
    const float* src  = (const float*)d_in[0];
    const float* ln1w = (const float*)d_in[1];
    const float* ln1b = (const float*)d_in[2];
    const float* wqkv = (const float*)d_in[3];
    const float* bqkv = (const float*)d_in[4];
    const float* wo   = (const float*)d_in[5];
    const float* bo   = (const float*)d_in[6];
    const float* ln2w = (const float*)d_in[7];
    const float* ln2b = (const float*)d_in[8];
    const float* w1   = (const float*)d_in[9];
    const float* b1   = (const float*)d_in[10];
    const float* w2   = (const float*)d_in[11];
    const float* b2   = (const float*)d_in[12];
    float* out = (float*)d_out;

    float *xn, *qkv, *ctx, *src2, *ff1;
    cudaGetSymbolAddress((void**)&xn,   g_xn);
    cudaGetSymbolAddress((void**)&qkv,  g_qkv);
    cudaGetSymbolAddress((void**)&ctx,  g_ctx);
    cudaGetSymbolAddress((void**)&src2, g_src2);
    cudaGetSymbolAddress((void**)&ff1,  g_ff1);

    cudaFuncSetAttribute(attn_kernel,
                         cudaFuncAttributeMaxDynamicSharedMemorySize, ATTN_SMEM);

    // 1) LN1
    ln_kernel<<<NTOK, 256>>>(src, ln1w, ln1b, xn);
    // 2) QKV projection
    gemm_kernel<<<dim3(3 * D_MODEL / 128, NTOK / 128), 256>>>(
        xn, wqkv, bqkv, nullptr, qkv, NTOK, 3 * D_MODEL, D_MODEL, 0);
    // 3) attention
    attn_kernel<<<dim3(SEQ / 64, NH, BATCH), 256, ATTN_SMEM>>>(qkv, ctx);
    // 4) output projection + residual
    gemm_kernel<<<dim3(D_MODEL / 128, NTOK / 128), 256>>>(
        ctx, wo, bo, src, src2, NTOK, D_MODEL, D_MODEL, 0);
    // 5) LN2
    ln_kernel<<<NTOK, 256>>>(src2, ln2w, ln2b, xn);
    // 6) FFN up + ReLU
    gemm_kernel<<<dim3(DFF / 128, NTOK / 128), 256>>>(
        xn, w1, b1, nullptr, ff1, NTOK, DFF, D_MODEL, 1);
    // 7) FFN down + residual -> out
    gemm_kernel<<<dim3(D_MODEL / 128, NTOK / 128), 256>>>(
        ff1, w2, b2, src2, out, NTOK, D_MODEL, DFF, 0);
}

// round 3
// speedup vs baseline: 2.0244x; 2.0244x over previous
#include <cuda_runtime.h>
#include <cstdint>
#include <math.h>

#define D_MODEL 1024
#define NH      16
#define DFF     4096
#define SEQ     2048
#define BATCH   2
#define NTOK    (BATCH*SEQ)          // 4096
#define NEG_BIG (-1e30f)

// ---------------- scratch (allocation-free rule: __device__ globals) --------
__device__ float g_xn  [NTOK * D_MODEL];
__device__ float g_qkv [NTOK * 3 * D_MODEL];
__device__ float g_ctx [NTOK * D_MODEL];
__device__ float g_src2[NTOK * D_MODEL];
__device__ float g_ff1 [NTOK * DFF];

// ---------------- helpers ----------------------------------------------------
__device__ __forceinline__ uint32_t f2tf32(float f) {
    uint32_t r;
    asm("cvt.rna.tf32.f32 %0, %1;" : "=r"(r) : "f"(f));
    return r;
}
__device__ __forceinline__ void mma_tf32(float c[4], uint32_t a0, uint32_t a1,
                                         uint32_t a2, uint32_t a3,
                                         uint32_t b0, uint32_t b1) {
    asm volatile(
        "mma.sync.aligned.m16n8k8.row.col.f32.tf32.tf32.f32 "
        "{%0,%1,%2,%3}, {%4,%5,%6,%7}, {%8,%9}, {%0,%1,%2,%3};"
        : "+f"(c[0]), "+f"(c[1]), "+f"(c[2]), "+f"(c[3])
        : "r"(a0), "r"(a1), "r"(a2), "r"(a3), "r"(b0), "r"(b1));
}

// ---------------- LayerNorm --------------------------------------------------
__global__ __launch_bounds__(256) void ln_kernel(
    const float* __restrict__ x, const float* __restrict__ w,
    const float* __restrict__ b, float* __restrict__ y)
{
    const int row = blockIdx.x;
    const int tid = threadIdx.x;
    const float* xr = x + (size_t)row * D_MODEL;

    float4 v = *(const float4*)&xr[tid * 4];
    float s  = v.x + v.y + v.z + v.w;
    float ss = v.x*v.x + v.y*v.y + v.z*v.z + v.w*v.w;
    #pragma unroll
    for (int o = 16; o > 0; o >>= 1) {
        s  += __shfl_xor_sync(0xffffffffu, s,  o);
        ss += __shfl_xor_sync(0xffffffffu, ss, o);
    }
    __shared__ float rs[8], rss[8];
    if ((tid & 31) == 0) { rs[tid >> 5] = s; rss[tid >> 5] = ss; }
    __syncthreads();
    float ts = 0.f, tss = 0.f;
    #pragma unroll
    for (int i = 0; i < 8; i++) { ts += rs[i]; tss += rss[i]; }

    const float mu  = ts * (1.0f / D_MODEL);
    const float var = fmaxf(tss * (1.0f / D_MODEL) - mu * mu, 0.0f);
    const float inv = rsqrtf(var + 1e-5f);

    float4 wv = *(const float4*)&w[tid * 4];
    float4 bv = *(const float4*)&b[tid * 4];
    float4 o;
    o.x = (v.x - mu) * inv * wv.x + bv.x;
    o.y = (v.y - mu) * inv * wv.y + bv.y;
    o.z = (v.z - mu) * inv * wv.z + bv.z;
    o.w = (v.w - mu) * inv * wv.w + bv.w;
    *(float4*)&(y + (size_t)row * D_MODEL)[tid * 4] = o;
}

// ---------------- tf32 mma.sync GEMM ----------------------------------------
// C[M,N] = A[M,K] @ B[K,N] + bias (+ReLU) (+res). B in native [K][N] layout.
// 128x128 tile, BK=32, 256 threads (8 warps, 2x4), warp tile 64x32.
#define PADA 36    // A_s: [m 0..127][k 0..31] stride 36
#define PADB 136   // B_s: [k 0..31][n 0..127] stride 136
#define ABUF (128 * PADA)            // 4608 words
#define BBUF (32 * PADB)             // 4352 words
#define GBUF (ABUF + BBUF)           // 8960 words per stage
#define GEMM_SMEM (2 * GBUF * 4)     // 71680 bytes

__global__ __launch_bounds__(256) void gemm_mma(
    const float* __restrict__ A, const float* __restrict__ B,
    const float* __restrict__ bias, const float* __restrict__ res,
    float* __restrict__ C, int M, int N, int K, int relu)
{
    extern __shared__ uint32_t sm_u[];

    const int tid  = threadIdx.x;
    const int wid  = tid >> 5;
    const int lane = tid & 31;
    const int gid  = lane >> 2;       // 0..7
    const int tig  = lane & 3;        // 0..3
    const int wm   = (wid >> 2) * 64; // warp row offset in tile
    const int wn   = (wid & 3) * 32;  // warp col offset in tile
    const int bm   = blockIdx.y * 128;
    const int bn   = blockIdx.x * 128;

    // loader indices
    const int ar = tid >> 3;          // wait: need idx per-it; computed in loop
    const int ac4 = tid & 7;
    const int bk = tid >> 5;          // wid
    const int bc4 = tid & 31;

    float acc[4][4][4];
    #pragma unroll
    for (int mt = 0; mt < 4; mt++)
        #pragma unroll
        for (int nt = 0; nt < 4; nt++)
            #pragma unroll
            for (int r = 0; r < 4; r++) acc[mt][nt][r] = 0.f;

    const int KC = K >> 5;

    // --- prologue: load chunk 0 into stage 0 ---
    {
        uint32_t* As = sm_u;
        uint32_t* Bs = sm_u + ABUF;
        #pragma unroll
        for (int it = 0; it < 4; it++) {
            const int idx = tid + it * 256;
            const int r = idx >> 3, c4 = idx & 7;
            float4 v = *(const float4*)&A[(size_t)(bm + r) * K + c4 * 4];
            uint4 w = { f2tf32(v.x), f2tf32(v.y), f2tf32(v.z), f2tf32(v.w) };
            *(uint4*)&As[r * PADA + c4 * 4] = w;
        }
        #pragma unroll
        for (int it = 0; it < 4; it++) {
            const int idx = tid + it * 256;
            const int k = idx >> 5, c4 = idx & 31;
            float4 v = *(const float4*)&B[(size_t)k * N + bn + c4 * 4];
            uint4 w = { f2tf32(v.x), f2tf32(v.y), f2tf32(v.z), f2tf32(v.w) };
            *(uint4*)&Bs[k * PADB + c4 * 4] = w;
        }
    }
    __syncthreads();

    for (int kc = 0; kc < KC; kc++) {
        const int buf = kc & 1;
        const uint32_t* As = sm_u + buf * GBUF;
        const uint32_t* Bs = sm_u + buf * GBUF + ABUF;

        // prefetch next chunk into registers
        float4 pa[4], pb[4];
        if (kc + 1 < KC) {
            const int k0 = (kc + 1) * 32;
            #pragma unroll
            for (int it = 0; it < 4; it++) {
                const int idx = tid + it * 256;
                const int r = idx >> 3, c4 = idx & 7;
                pa[it] = *(const float4*)&A[(size_t)(bm + r) * K + k0 + c4 * 4];
            }
            #pragma unroll
            for (int it = 0; it < 4; it++) {
                const int idx = tid + it * 256;
                const int k = idx >> 5, c4 = idx & 31;
                pb[it] = *(const float4*)&B[(size_t)(k0 + k) * N + bn + c4 * 4];
            }
        }

        // compute 4 k-steps of m16n8k8
        #pragma unroll
        for (int ko = 0; ko < 4; ko++) {
            const int kk = ko * 8;
            uint32_t a[4][4];
            #pragma unroll
            for (int mt = 0; mt < 4; mt++) {
                const int m = wm + mt * 16 + gid;
                a[mt][0] = As[(m    ) * PADA + kk + tig];
                a[mt][1] = As[(m + 8) * PADA + kk + tig];
                a[mt][2] = As[(m    ) * PADA + kk + tig + 4];
                a[mt][3] = As[(m + 8) * PADA + kk + tig + 4];
            }
            uint32_t bfr[4][2];
            #pragma unroll
            for (int nt = 0; nt < 4; nt++) {
                const int n = wn + nt * 8 + gid;
                bfr[nt][0] = Bs[(kk + tig    ) * PADB + n];
                bfr[nt][1] = Bs[(kk + tig + 4) * PADB + n];
            }
            #pragma unroll
            for (int mt = 0; mt < 4; mt++)
                #pragma unroll
                for (int nt = 0; nt < 4; nt++)
                    mma_tf32(acc[mt][nt], a[mt][0], a[mt][1], a[mt][2], a[mt][3],
                             bfr[nt][0], bfr[nt][1]);
        }

        // store prefetched chunk into alternate stage
        if (kc + 1 < KC) {
            uint32_t* As1 = sm_u + (buf ^ 1) * GBUF;
            uint32_t* Bs1 = sm_u + (buf ^ 1) * GBUF + ABUF;
            #pragma unroll
            for (int it = 0; it < 4; it++) {
                const int idx = tid + it * 256;
                const int r = idx >> 3, c4 = idx & 7;
                uint4 w = { f2tf32(pa[it].x), f2tf32(pa[it].y),
                            f2tf32(pa[it].z), f2tf32(pa[it].w) };
                *(uint4*)&As1[r * PADA + c4 * 4] = w;
            }
            #pragma unroll
            for (int it = 0; it < 4; it++) {
                const int idx = tid + it * 256;
                const int k = idx >> 5, c4 = idx & 31;
                uint4 w = { f2tf32(pb[it].x), f2tf32(pb[it].y),
                            f2tf32(pb[it].z), f2tf32(pb[it].w) };
                *(uint4*)&Bs1[k * PADB + c4 * 4] = w;
            }
        }
        __syncthreads();
    }

    // --- epilogue ---
    #pragma unroll
    for (int mt = 0; mt < 4; mt++) {
        #pragma unroll
        for (int r2 = 0; r2 < 2; r2++) {
            const int m = bm + wm + mt * 16 + gid + r2 * 8;
            #pragma unroll
            for (int nt = 0; nt < 4; nt++) {
                const int n = bn + wn + nt * 8 + tig * 2;
                float2 bv = *(const float2*)&bias[n];
                float2 o;
                o.x = acc[mt][nt][r2 * 2 + 0] + bv.x;
                o.y = acc[mt][nt][r2 * 2 + 1] + bv.y;
                if (relu) { o.x = fmaxf(o.x, 0.f); o.y = fmaxf(o.y, 0.f); }
                if (res) {
                    float2 rv = *(const float2*)&res[(size_t)m * N + n];
                    o.x += rv.x; o.y += rv.y;
                }
                *(float2*)&C[(size_t)m * N + n] = o;
            }
        }
    }
}

// ---------------- Flash attention with ALiBi + causal -----------------------
#define ASTRIDE 68
#define ATTN_SMEM (4 * 64 * ASTRIDE * (int)sizeof(float))

__global__ __launch_bounds__(256) void attn_kernel(
    const float* __restrict__ qkv, float* __restrict__ ctx)
{
    extern __shared__ float sm[];
    float* Qs = sm;
    float* Ks = sm + 1 * 64 * ASTRIDE;
    float* Vs = sm + 2 * 64 * ASTRIDE;
    float* Ps = sm + 3 * 64 * ASTRIDE;

    const int qt = blockIdx.x, h = blockIdx.y, b = blockIdx.z;
    const int tid = threadIdx.x;
    const int tx = tid & 15, ty = tid >> 4;
    const int r0 = ty * 4, c0 = tx * 4;
    const int q_base = qt * 64;
    const size_t tok0 = (size_t)b * SEQ;
    const float scale = 0.125f;
    const float slope = -exp2f(-(float)h);

    for (int i = tid; i < 64 * 16; i += 256) {
        const int r = i >> 4, d = (i & 15) * 4;
        float4 v = *(const float4*)&qkv[(tok0 + q_base + r) * 3072 + h * 64 + d];
        Qs[(d + 0) * ASTRIDE + r] = v.x; Qs[(d + 1) * ASTRIDE + r] = v.y;
        Qs[(d + 2) * ASTRIDE + r] = v.z; Qs[(d + 3) * ASTRIDE + r] = v.w;
    }

    float m_run[4], l_run[4], acc[4][4];
    #pragma unroll
    for (int i = 0; i < 4; i++) {
        m_run[i] = NEG_BIG; l_run[i] = 0.f;
        #pragma unroll
        for (int j = 0; j < 4; j++) acc[i][j] = 0.f;
    }
    __syncthreads();

    for (int kt = 0; kt <= qt; kt++) {
        const int k_base = kt * 64;
        for (int i = tid; i < 64 * 16; i += 256) {
            const int j = i >> 4, d = (i & 15) * 4;
            const float* base = &qkv[(tok0 + k_base + j) * 3072 + h * 64 + d];
            float4 kv = *(const float4*)(base + 1024);
            Ks[(d + 0) * ASTRIDE + j] = kv.x; Ks[(d + 1) * ASTRIDE + j] = kv.y;
            Ks[(d + 2) * ASTRIDE + j] = kv.z; Ks[(d + 3) * ASTRIDE + j] = kv.w;
            *(float4*)&Vs[j * ASTRIDE + d] = *(const float4*)(base + 2048);
        }
        __syncthreads();

        float s[4][4];
        #pragma unroll
        for (int i = 0; i < 4; i++)
            #pragma unroll
            for (int j = 0; j < 4; j++) s[i][j] = 0.f;
        #pragma unroll 8
        for (int d = 0; d < 64; d++) {
            float4 qa = *(const float4*)&Qs[d * ASTRIDE + r0];
            float4 kb = *(const float4*)&Ks[d * ASTRIDE + c0];
            const float qv[4] = {qa.x, qa.y, qa.z, qa.w};
            const float kv[4] = {kb.x, kb.y, kb.z, kb.w};
            #pragma unroll
            for (int i = 0; i < 4; i++)
                #pragma unroll
                for (int j = 0; j < 4; j++)
                    s[i][j] = fmaf(qv[i], kv[j], s[i][j]);
        }

        const bool diag = (kt == qt);
        #pragma unroll
        for (int i = 0; i < 4; i++) {
            const int qi = q_base + r0 + i;
            float rowmax = NEG_BIG;
            #pragma unroll
            for (int j = 0; j < 4; j++) {
                const int kj = k_base + c0 + j;
                float v = fmaf(s[i][j], scale, (float)(qi + kj) * slope);
                if (diag && kj > qi) v = NEG_BIG;
                s[i][j] = v;
                rowmax = fmaxf(rowmax, v);
            }
            #pragma unroll
            for (int o = 1; o < 16; o <<= 1)
                rowmax = fmaxf(rowmax, __shfl_xor_sync(0xffffffffu, rowmax, o));
            const float m_new = fmaxf(m_run[i], rowmax);
            const float corr = __expf(m_run[i] - m_new);
            float ps = 0.f;
            #pragma unroll
            for (int j = 0; j < 4; j++) {
                const float p = __expf(s[i][j] - m_new);
                s[i][j] = p; ps += p;
            }
            #pragma unroll
            for (int o = 1; o < 16; o <<= 1)
                ps += __shfl_xor_sync(0xffffffffu, ps, o);
            l_run[i] = l_run[i] * corr + ps;
            m_run[i] = m_new;
            #pragma unroll
            for (int j = 0; j < 4; j++) acc[i][j] *= corr;
        }

        #pragma unroll
        for (int i = 0; i < 4; i++)
            #pragma unroll
            for (int j = 0; j < 4; j++)
                Ps[(c0 + j) * ASTRIDE + (r0 + i)] = s[i][j];
        __syncthreads();

        #pragma unroll 8
        for (int k = 0; k < 64; k++) {
            float4 pa = *(const float4*)&Ps[k * ASTRIDE + r0];
            float4 vb = *(const float4*)&Vs[k * ASTRIDE + c0];
            const float pv[4] = {pa.x, pa.y, pa.z, pa.w};
            const float vv[4] = {vb.x, vb.y, vb.z, vb.w};
            #pragma unroll
            for (int i = 0; i < 4; i++)
                #pragma unroll
                for (int j = 0; j < 4; j++)
                    acc[i][j] = fmaf(pv[i], vv[j], acc[i][j]);
        }
        __syncthreads();
    }

    #pragma unroll
    for (int i = 0; i < 4; i++) {
        const float inv = 1.0f / l_run[i];
        float4 o = make_float4(acc[i][0] * inv, acc[i][1] * inv,
                               acc[i][2] * inv, acc[i][3] * inv);
        *(float4*)&ctx[(tok0 + q_base + r0 + i) * D_MODEL + h * 64 + c0] = o;
    }
}

// ---------------- launch ----------------------------------------------------
extern "C" void kernel_launch(void* const* d_in, const int* in_sizes, int n_in,
                              void* d_out, int out_size)
{
    const float* src  = (const float*)d_in[0];
    const float* ln1w = (const float*)d_in[1];
    const float* ln1b = (const float*)d_in[2];
    const float* wqkv = (const float*)d_in[3];
    const float* bqkv = (const float*)d_in[4];
    const float* wo   = (const float*)d_in[5];
    const float* bo   = (const float*)d_in[6];
    const float* ln2w = (const float*)d_in[7];
    const float* ln2b = (const float*)d_in[8];
    const float* w1   = (const float*)d_in[9];
    const float* b1   = (const float*)d_in[10];
    const float* w2   = (const float*)d_in[11];
    const float* b2   = (const float*)d_in[12];
    float* out = (float*)d_out;

    float *xn, *qkv, *ctx, *src2, *ff1;
    cudaGetSymbolAddress((void**)&xn,   g_xn);
    cudaGetSymbolAddress((void**)&qkv,  g_qkv);
    cudaGetSymbolAddress((void**)&ctx,  g_ctx);
    cudaGetSymbolAddress((void**)&src2, g_src2);
    cudaGetSymbolAddress((void**)&ff1,  g_ff1);

    cudaFuncSetAttribute(attn_kernel,
                         cudaFuncAttributeMaxDynamicSharedMemorySize, ATTN_SMEM);
    cudaFuncSetAttribute(gemm_mma,
                         cudaFuncAttributeMaxDynamicSharedMemorySize, GEMM_SMEM);

    // 1) LN1
    ln_kernel<<<NTOK, 256>>>(src, ln1w, ln1b, xn);
    // 2) QKV projection
    gemm_mma<<<dim3(3 * D_MODEL / 128, NTOK / 128), 256, GEMM_SMEM>>>(
        xn, wqkv, bqkv, nullptr, qkv, NTOK, 3 * D_MODEL, D_MODEL, 0);
    // 3) attention
    attn_kernel<<<dim3(SEQ / 64, NH, BATCH), 256, ATTN_SMEM>>>(qkv, ctx);
    // 4) output projection + residual
    gemm_mma<<<dim3(D_MODEL / 128, NTOK / 128), 256, GEMM_SMEM>>>(
        ctx, wo, bo, src, src2, NTOK, D_MODEL, D_MODEL, 0);
    // 5) LN2
    ln_kernel<<<NTOK, 256>>>(src2, ln2w, ln2b, xn);
    // 6) FFN up + ReLU
    gemm_mma<<<dim3(DFF / 128, NTOK / 128), 256, GEMM_SMEM>>>(
        xn, w1, b1, nullptr, ff1, NTOK, DFF, D_MODEL, 1);
    // 7) FFN down + residual -> out
    gemm_mma<<<dim3(D_MODEL / 128, NTOK / 128), 256, GEMM_SMEM>>>(
        ff1, w2, b2, src2, out, NTOK, D_MODEL, DFF, 0);
}

// round 4
// speedup vs baseline: 3.4758x; 1.7170x over previous
#include <cuda_runtime.h>
#include <cstdint>
#include <math.h>

#define D_MODEL 1024
#define NH      16
#define DFF     4096
#define SEQ     2048
#define BATCH   2
#define NTOK    (BATCH*SEQ)          // 4096
#define NEG_BIG (-1e30f)

// ---------------- scratch (allocation-free rule: __device__ globals) --------
__device__ float g_xn  [NTOK * D_MODEL];
__device__ float g_qkv [NTOK * 3 * D_MODEL];
__device__ float g_ctx [NTOK * D_MODEL];
__device__ float g_src2[NTOK * D_MODEL];
__device__ float g_ff1 [NTOK * DFF];

// ---------------- helpers ----------------------------------------------------
__device__ __forceinline__ uint32_t f2tf32(float f) {
    uint32_t r;
    asm("cvt.rna.tf32.f32 %0, %1;" : "=r"(r) : "f"(f));
    return r;
}
__device__ __forceinline__ uint32_t bits2tf32(uint32_t raw) {
    return f2tf32(__uint_as_float(raw));
}
__device__ __forceinline__ void mma_tf32(float c[4], uint32_t a0, uint32_t a1,
                                         uint32_t a2, uint32_t a3,
                                         uint32_t b0, uint32_t b1) {
    asm volatile(
        "mma.sync.aligned.m16n8k8.row.col.f32.tf32.tf32.f32 "
        "{%0,%1,%2,%3}, {%4,%5,%6,%7}, {%8,%9}, {%0,%1,%2,%3};"
        : "+f"(c[0]), "+f"(c[1]), "+f"(c[2]), "+f"(c[3])
        : "r"(a0), "r"(a1), "r"(a2), "r"(a3), "r"(b0), "r"(b1));
}
__device__ __forceinline__ uint32_t smem_u32(const void* p) {
    uint32_t a;
    asm("{ .reg .u64 t; cvta.to.shared.u64 t, %1; cvt.u32.u64 %0, t; }"
        : "=r"(a) : "l"(p));
    return a;
}
__device__ __forceinline__ void cp_async16(uint32_t dst, const void* src) {
    asm volatile("cp.async.cg.shared.global [%0], [%1], 16;"
                 :: "r"(dst), "l"(src) : "memory");
}
__device__ __forceinline__ void cp_commit() {
    asm volatile("cp.async.commit_group;" ::: "memory");
}

// ---------------- LayerNorm --------------------------------------------------
__global__ __launch_bounds__(256) void ln_kernel(
    const float* __restrict__ x, const float* __restrict__ w,
    const float* __restrict__ b, float* __restrict__ y)
{
    const int row = blockIdx.x;
    const int tid = threadIdx.x;
    const float* xr = x + (size_t)row * D_MODEL;

    float4 v = *(const float4*)&xr[tid * 4];
    float s  = v.x + v.y + v.z + v.w;
    float ss = v.x*v.x + v.y*v.y + v.z*v.z + v.w*v.w;
    #pragma unroll
    for (int o = 16; o > 0; o >>= 1) {
        s  += __shfl_xor_sync(0xffffffffu, s,  o);
        ss += __shfl_xor_sync(0xffffffffu, ss, o);
    }
    __shared__ float rs[8], rss[8];
    if ((tid & 31) == 0) { rs[tid >> 5] = s; rss[tid >> 5] = ss; }
    __syncthreads();
    float ts = 0.f, tss = 0.f;
    #pragma unroll
    for (int i = 0; i < 8; i++) { ts += rs[i]; tss += rss[i]; }

    const float mu  = ts * (1.0f / D_MODEL);
    const float var = fmaxf(tss * (1.0f / D_MODEL) - mu * mu, 0.0f);
    const float inv = rsqrtf(var + 1e-5f);

    float4 wv = *(const float4*)&w[tid * 4];
    float4 bv = *(const float4*)&b[tid * 4];
    float4 o;
    o.x = (v.x - mu) * inv * wv.x + bv.x;
    o.y = (v.y - mu) * inv * wv.y + bv.y;
    o.z = (v.z - mu) * inv * wv.z + bv.z;
    o.w = (v.w - mu) * inv * wv.w + bv.w;
    *(float4*)&(y + (size_t)row * D_MODEL)[tid * 4] = o;
}

// ---------------- tf32 mma.sync GEMM with cp.async 3-stage pipeline ---------
// C[M,N] = A[M,K] @ B[K,N] + bias (+ReLU) (+res). B native [K][N].
// 128x128 tile, BK=32, 256 threads (8 warps 2x4), warp tile 64x32.
#define PADA 36
#define PADB 136
#define ABUF (128 * PADA)              // 4608 words
#define BBUF (32 * PADB)               // 4352 words
#define STAGE_WORDS (ABUF + BBUF)      // 8960 words
#define STAGES 3
#define GEMM_SMEM (STAGES * STAGE_WORDS * 4)   // 107520 bytes

__device__ __forceinline__ void gemm_load_stage(
    const float* __restrict__ A, const float* __restrict__ B,
    int N, int K, int bm, int bn, int k0, uint32_t sA, uint32_t sB, int tid)
{
    #pragma unroll
    for (int it = 0; it < 4; it++) {
        const int idx = tid + it * 256;
        const int r = idx >> 3, c4 = idx & 7;
        cp_async16(sA + (uint32_t)(r * PADA + c4 * 4) * 4,
                   &A[(size_t)(bm + r) * K + k0 + c4 * 4]);
    }
    #pragma unroll
    for (int it = 0; it < 4; it++) {
        const int idx = tid + it * 256;
        const int k = idx >> 5, c4 = idx & 31;
        cp_async16(sB + (uint32_t)(k * PADB + c4 * 4) * 4,
                   &B[(size_t)(k0 + k) * N + bn + c4 * 4]);
    }
}

__global__ __launch_bounds__(256, 2) void gemm_mma(
    const float* __restrict__ A, const float* __restrict__ B,
    const float* __restrict__ bias, const float* __restrict__ res,
    float* __restrict__ C, int M, int N, int K, int relu)
{
    extern __shared__ uint32_t sm_u[];

    const int tid  = threadIdx.x;
    const int wid  = tid >> 5;
    const int lane = tid & 31;
    const int gid  = lane >> 2;
    const int tig  = lane & 3;
    const int wm   = (wid >> 2) * 64;
    const int wn   = (wid & 3) * 32;
    const int bm   = blockIdx.y * 128;
    const int bn   = blockIdx.x * 128;

    const uint32_t smem_base = smem_u32(sm_u);

    float acc[4][4][4];
    #pragma unroll
    for (int mt = 0; mt < 4; mt++)
        #pragma unroll
        for (int nt = 0; nt < 4; nt++)
            #pragma unroll
            for (int r = 0; r < 4; r++) acc[mt][nt][r] = 0.f;

    const int KC = K >> 5;

    // prologue: stages 0 and 1
    gemm_load_stage(A, B, N, K, bm, bn, 0,
                    smem_base, smem_base + ABUF * 4, tid);
    cp_commit();
    gemm_load_stage(A, B, N, K, bm, bn, 32,
                    smem_base + STAGE_WORDS * 4,
                    smem_base + STAGE_WORDS * 4 + ABUF * 4, tid);
    cp_commit();

    int stage = 0;
    for (int kc = 0; kc < KC; kc++) {
        if (kc + 1 < KC) asm volatile("cp.async.wait_group 1;" ::: "memory");
        else             asm volatile("cp.async.wait_group 0;" ::: "memory");
        __syncthreads();

        const uint32_t* As = sm_u + stage * STAGE_WORDS;
        const uint32_t* Bs = As + ABUF;

        #pragma unroll
        for (int ko = 0; ko < 4; ko++) {
            const int kk = ko * 8;
            uint32_t a[4][4];
            #pragma unroll
            for (int mt = 0; mt < 4; mt++) {
                const int m = wm + mt * 16 + gid;
                a[mt][0] = bits2tf32(As[(m    ) * PADA + kk + tig]);
                a[mt][1] = bits2tf32(As[(m + 8) * PADA + kk + tig]);
                a[mt][2] = bits2tf32(As[(m    ) * PADA + kk + tig + 4]);
                a[mt][3] = bits2tf32(As[(m + 8) * PADA + kk + tig + 4]);
            }
            uint32_t bf[4][2];
            #pragma unroll
            for (int nt = 0; nt < 4; nt++) {
                const int n = wn + nt * 8 + gid;
                bf[nt][0] = bits2tf32(Bs[(kk + tig    ) * PADB + n]);
                bf[nt][1] = bits2tf32(Bs[(kk + tig + 4) * PADB + n]);
            }
            #pragma unroll
            for (int mt = 0; mt < 4; mt++)
                #pragma unroll
                for (int nt = 0; nt < 4; nt++)
                    mma_tf32(acc[mt][nt], a[mt][0], a[mt][1], a[mt][2], a[mt][3],
                             bf[nt][0], bf[nt][1]);
        }

        if (kc + 2 < KC) {
            const int ns = (stage + 2 >= STAGES) ? stage + 2 - STAGES : stage + 2;
            const uint32_t sA = smem_base + (uint32_t)ns * STAGE_WORDS * 4;
            gemm_load_stage(A, B, N, K, bm, bn, (kc + 2) * 32,
                            sA, sA + ABUF * 4, tid);
            cp_commit();
        }
        stage = (stage + 1 == STAGES) ? 0 : stage + 1;
    }

    // epilogue
    #pragma unroll
    for (int mt = 0; mt < 4; mt++) {
        #pragma unroll
        for (int r2 = 0; r2 < 2; r2++) {
            const int m = bm + wm + mt * 16 + gid + r2 * 8;
            #pragma unroll
            for (int nt = 0; nt < 4; nt++) {
                const int n = bn + wn + nt * 8 + tig * 2;
                float2 bv = *(const float2*)&bias[n];
                float2 o;
                o.x = acc[mt][nt][r2 * 2 + 0] + bv.x;
                o.y = acc[mt][nt][r2 * 2 + 1] + bv.y;
                if (relu) { o.x = fmaxf(o.x, 0.f); o.y = fmaxf(o.y, 0.f); }
                if (res) {
                    float2 rv = *(const float2*)&res[(size_t)m * N + n];
                    o.x += rv.x; o.y += rv.y;
                }
                *(float2*)&C[(size_t)m * N + n] = o;
            }
        }
    }
}

// ---------------- Tensor-core flash attention (ALiBi + causal) --------------
// Block: 64 q-rows x (head, batch). 128 threads = 4 warps, warp owns 16 rows.
// Smem: Ks, Vs, Ps each [64][72] fp32/tf32 bits. Q fragments in registers.
#define AT_S 72
#define ATTN_SMEM (3 * 64 * AT_S * (int)sizeof(float))

__global__ __launch_bounds__(128, 3) void attn_tc(
    const float* __restrict__ qkv, float* __restrict__ ctx)
{
    extern __shared__ float sm[];
    uint32_t* Ku = (uint32_t*)sm;
    uint32_t* Vu = Ku + 64 * AT_S;
    uint32_t* Pu = Vu + 64 * AT_S;

    const int qt = blockIdx.x, h = blockIdx.y, b = blockIdx.z;
    const int tid  = threadIdx.x;
    const int w    = tid >> 5;
    const int lane = tid & 31;
    const int gid  = lane >> 2;
    const int tig  = lane & 3;
    const int wm   = w * 16;
    const int q_base = qt * 64;
    const size_t tok0 = (size_t)b * SEQ;
    const float scale = 0.125f;                     // 1/sqrt(64)
    const float slope = -exp2f(-(float)h);

    // Q fragments in registers (rows wm+gid, wm+gid+8; cols ko*8+tig(+4))
    uint32_t qa[8][4];
    {
        const float* q0 = &qkv[(tok0 + q_base + wm + gid    ) * 3072 + h * 64];
        const float* q1 = &qkv[(tok0 + q_base + wm + gid + 8) * 3072 + h * 64];
        #pragma unroll
        for (int ko = 0; ko < 8; ko++) {
            qa[ko][0] = f2tf32(q0[ko * 8 + tig]);
            qa[ko][1] = f2tf32(q1[ko * 8 + tig]);
            qa[ko][2] = f2tf32(q0[ko * 8 + tig + 4]);
            qa[ko][3] = f2tf32(q1[ko * 8 + tig + 4]);
        }
    }

    float m_run[2] = {NEG_BIG, NEG_BIG};
    float l_run[2] = {0.f, 0.f};
    float oa[8][4];
    #pragma unroll
    for (int nt = 0; nt < 8; nt++)
        #pragma unroll
        for (int r = 0; r < 4; r++) oa[nt][r] = 0.f;

    const int i0 = q_base + wm + gid;
    const int i1 = i0 + 8;

    for (int kt = 0; kt <= qt; kt++) {
        const int k_base = kt * 64;
        // load K,V tiles (tf32-rounded)
        for (int i = tid; i < 64 * 16; i += 128) {
            const int r = i >> 4, c4 = (i & 15) * 4;
            const float* base = &qkv[(tok0 + k_base + r) * 3072 + h * 64 + c4];
            float4 kv = *(const float4*)(base + 1024);
            float4 vv = *(const float4*)(base + 2048);
            uint4 ku = { f2tf32(kv.x), f2tf32(kv.y), f2tf32(kv.z), f2tf32(kv.w) };
            uint4 vu = { f2tf32(vv.x), f2tf32(vv.y), f2tf32(vv.z), f2tf32(vv.w) };
            *(uint4*)&Ku[r * AT_S + c4] = ku;
            *(uint4*)&Vu[r * AT_S + c4] = vu;
        }
        __syncthreads();

        // S = Q K^T : warp computes rows [wm, wm+16), all 64 cols
        float sf[8][4];
        #pragma unroll
        for (int nt = 0; nt < 8; nt++)
            #pragma unroll
            for (int r = 0; r < 4; r++) sf[nt][r] = 0.f;
        #pragma unroll
        for (int ko = 0; ko < 8; ko++) {
            const int kk = ko * 8;
            #pragma unroll
            for (int nt = 0; nt < 8; nt++) {
                const uint32_t b0 = Ku[(nt * 8 + gid) * AT_S + kk + tig];
                const uint32_t b1 = Ku[(nt * 8 + gid) * AT_S + kk + tig + 4];
                mma_tf32(sf[nt], qa[ko][0], qa[ko][1], qa[ko][2], qa[ko][3], b0, b1);
            }
        }

        // softmax over the 64 columns of this k-tile
        const bool diag = (kt == qt);
        float mx0 = NEG_BIG, mx1 = NEG_BIG;
        #pragma unroll
        for (int nt = 0; nt < 8; nt++) {
            const int j0 = k_base + nt * 8 + tig * 2;
            float v0 = fmaf(sf[nt][0], scale, (float)(i0 + j0    ) * slope);
            float v1 = fmaf(sf[nt][1], scale, (float)(i0 + j0 + 1) * slope);
            float v2 = fmaf(sf[nt][2], scale, (float)(i1 + j0    ) * slope);
            float v3 = fmaf(sf[nt][3], scale, (float)(i1 + j0 + 1) * slope);
            if (diag) {
                if (j0     > i0) v0 = NEG_BIG;
                if (j0 + 1 > i0) v1 = NEG_BIG;
                if (j0     > i1) v2 = NEG_BIG;
                if (j0 + 1 > i1) v3 = NEG_BIG;
            }
            sf[nt][0] = v0; sf[nt][1] = v1; sf[nt][2] = v2; sf[nt][3] = v3;
            mx0 = fmaxf(mx0, fmaxf(v0, v1));
            mx1 = fmaxf(mx1, fmaxf(v2, v3));
        }
        mx0 = fmaxf(mx0, __shfl_xor_sync(0xffffffffu, mx0, 1));
        mx0 = fmaxf(mx0, __shfl_xor_sync(0xffffffffu, mx0, 2));
        mx1 = fmaxf(mx1, __shfl_xor_sync(0xffffffffu, mx1, 1));
        mx1 = fmaxf(mx1, __shfl_xor_sync(0xffffffffu, mx1, 2));

        const float mn0 = fmaxf(m_run[0], mx0);
        const float mn1 = fmaxf(m_run[1], mx1);
        const float corr0 = __expf(m_run[0] - mn0);
        const float corr1 = __expf(m_run[1] - mn1);
        float s0 = 0.f, s1 = 0.f;
        #pragma unroll
        for (int nt = 0; nt < 8; nt++) {
            const float p0 = __expf(sf[nt][0] - mn0);
            const float p1 = __expf(sf[nt][1] - mn0);
            const float p2 = __expf(sf[nt][2] - mn1);
            const float p3 = __expf(sf[nt][3] - mn1);
            s0 += p0 + p1; s1 += p2 + p3;
            // store P (tf32-rounded) for the PV mma
            uint32_t* p0p = &Pu[(wm + gid    ) * AT_S + nt * 8 + tig * 2];
            uint32_t* p1p = &Pu[(wm + gid + 8) * AT_S + nt * 8 + tig * 2];
            p0p[0] = f2tf32(p0); p0p[1] = f2tf32(p1);
            p1p[0] = f2tf32(p2); p1p[1] = f2tf32(p3);
        }
        s0 += __shfl_xor_sync(0xffffffffu, s0, 1);
        s0 += __shfl_xor_sync(0xffffffffu, s0, 2);
        s1 += __shfl_xor_sync(0xffffffffu, s1, 1);
        s1 += __shfl_xor_sync(0xffffffffu, s1, 2);
        l_run[0] = l_run[0] * corr0 + s0;
        l_run[1] = l_run[1] * corr1 + s1;
        m_run[0] = mn0; m_run[1] = mn1;
        #pragma unroll
        for (int nt = 0; nt < 8; nt++) {
            oa[nt][0] *= corr0; oa[nt][1] *= corr0;
            oa[nt][2] *= corr1; oa[nt][3] *= corr1;
        }
        __syncthreads();

        // O += P V
        #pragma unroll
        for (int ko = 0; ko < 8; ko++) {
            const int kk = ko * 8;
            uint32_t a0 = Pu[(wm + gid    ) * AT_S + kk + tig];
            uint32_t a1 = Pu[(wm + gid + 8) * AT_S + kk + tig];
            uint32_t a2 = Pu[(wm + gid    ) * AT_S + kk + tig + 4];
            uint32_t a3 = Pu[(wm + gid + 8) * AT_S + kk + tig + 4];
            #pragma unroll
            for (int nt = 0; nt < 8; nt++) {
                const uint32_t b0 = Vu[(kk + tig    ) * AT_S + nt * 8 + gid];
                const uint32_t b1 = Vu[(kk + tig + 4) * AT_S + nt * 8 + gid];
                mma_tf32(oa[nt], a0, a1, a2, a3, b0, b1);
            }
        }
        __syncthreads();
    }

    // normalize and write ctx
    const float inv0 = 1.0f / l_run[0];
    const float inv1 = 1.0f / l_run[1];
    float* c0 = &ctx[(tok0 + q_base + wm + gid    ) * D_MODEL + h * 64];
    float* c1 = &ctx[(tok0 + q_base + wm + gid + 8) * D_MODEL + h * 64];
    #pragma unroll
    for (int nt = 0; nt < 8; nt++) {
        float2 o0 = { oa[nt][0] * inv0, oa[nt][1] * inv0 };
        float2 o1 = { oa[nt][2] * inv1, oa[nt][3] * inv1 };
        *(float2*)&c0[nt * 8 + tig * 2] = o0;
        *(float2*)&c1[nt * 8 + tig * 2] = o1;
    }
}

// ---------------- launch ----------------------------------------------------
extern "C" void kernel_launch(void* const* d_in, const int* in_sizes, int n_in,
                              void* d_out, int out_size)
{
    const float* src  = (const float*)d_in[0];
    const float* ln1w = (const float*)d_in[1];
    const float* ln1b = (const float*)d_in[2];
    const float* wqkv = (const float*)d_in[3];
    const float* bqkv = (const float*)d_in[4];
    const float* wo   = (const float*)d_in[5];
    const float* bo   = (const float*)d_in[6];
    const float* ln2w = (const float*)d_in[7];
    const float* ln2b = (const float*)d_in[8];
    const float* w1   = (const float*)d_in[9];
    const float* b1   = (const float*)d_in[10];
    const float* w2   = (const float*)d_in[11];
    const float* b2   = (const float*)d_in[12];
    float* out = (float*)d_out;

    float *xn, *qkv, *ctx, *src2, *ff1;
    cudaGetSymbolAddress((void**)&xn,   g_xn);
    cudaGetSymbolAddress((void**)&qkv,  g_qkv);
    cudaGetSymbolAddress((void**)&ctx,  g_ctx);
    cudaGetSymbolAddress((void**)&src2, g_src2);
    cudaGetSymbolAddress((void**)&ff1,  g_ff1);

    cudaFuncSetAttribute(attn_tc,
                         cudaFuncAttributeMaxDynamicSharedMemorySize, ATTN_SMEM);
    cudaFuncSetAttribute(gemm_mma,
                         cudaFuncAttributeMaxDynamicSharedMemorySize, GEMM_SMEM);

    // 1) LN1
    ln_kernel<<<NTOK, 256>>>(src, ln1w, ln1b, xn);
    // 2) QKV projection
    gemm_mma<<<dim3(3 * D_MODEL / 128, NTOK / 128), 256, GEMM_SMEM>>>(
        xn, wqkv, bqkv, nullptr, qkv, NTOK, 3 * D_MODEL, D_MODEL, 0);
    // 3) attention (tensor cores)
    attn_tc<<<dim3(SEQ / 64, NH, BATCH), 128, ATTN_SMEM>>>(qkv, ctx);
    // 4) output projection + residual
    gemm_mma<<<dim3(D_MODEL / 128, NTOK / 128), 256, GEMM_SMEM>>>(
        ctx, wo, bo, src, src2, NTOK, D_MODEL, D_MODEL, 0);
    // 5) LN2
    ln_kernel<<<NTOK, 256>>>(src2, ln2w, ln2b, xn);
    // 6) FFN up + ReLU
    gemm_mma<<<dim3(DFF / 128, NTOK / 128), 256, GEMM_SMEM>>>(
        xn, w1, b1, nullptr, ff1, NTOK, DFF, D_MODEL, 1);
    // 7) FFN down + residual -> out
    gemm_mma<<<dim3(D_MODEL / 128, NTOK / 128), 256, GEMM_SMEM>>>(
        ff1, w2, b2, src2, out, NTOK, D_MODEL, DFF, 0);
}

// round 5
// speedup vs baseline: 4.9292x; 1.4182x over previous
#include <cuda_runtime.h>
#include <cuda_fp16.h>
#include <cstdint>
#include <math.h>

#define D_MODEL 1024
#define NH      16
#define DFF     4096
#define SEQ     2048
#define BATCH   2
#define NTOK    (BATCH*SEQ)          // 4096
#define NEG_BIG (-1e30f)

// ---------------- scratch (allocation-free rule: __device__ globals) --------
__device__ __half g_xn_h [NTOK * D_MODEL];
__device__ float  g_qkv  [NTOK * 3 * D_MODEL];
__device__ __half g_ctx_h[NTOK * D_MODEL];
__device__ float  g_src2 [NTOK * D_MODEL];
__device__ __half g_ff1_h[NTOK * DFF];
__device__ __half g_wqkv_h[D_MODEL * 3 * D_MODEL];
__device__ __half g_wo_h  [D_MODEL * D_MODEL];
__device__ __half g_w1_h  [D_MODEL * DFF];
__device__ __half g_w2_h  [DFF * D_MODEL];

// ---------------- helpers ----------------------------------------------------
__device__ __forceinline__ uint32_t f2tf32(float f) {
    uint32_t r;
    asm("cvt.rna.tf32.f32 %0, %1;" : "=r"(r) : "f"(f));
    return r;
}
__device__ __forceinline__ void mma_tf32(float c[4], uint32_t a0, uint32_t a1,
                                         uint32_t a2, uint32_t a3,
                                         uint32_t b0, uint32_t b1) {
    asm volatile(
        "mma.sync.aligned.m16n8k8.row.col.f32.tf32.tf32.f32 "
        "{%0,%1,%2,%3}, {%4,%5,%6,%7}, {%8,%9}, {%0,%1,%2,%3};"
        : "+f"(c[0]), "+f"(c[1]), "+f"(c[2]), "+f"(c[3])
        : "r"(a0), "r"(a1), "r"(a2), "r"(a3), "r"(b0), "r"(b1));
}
__device__ __forceinline__ void mma_f16(float c[4], uint32_t a0, uint32_t a1,
                                        uint32_t a2, uint32_t a3,
                                        uint32_t b0, uint32_t b1) {
    asm volatile(
        "mma.sync.aligned.m16n8k16.row.col.f32.f16.f16.f32 "
        "{%0,%1,%2,%3}, {%4,%5,%6,%7}, {%8,%9}, {%0,%1,%2,%3};"
        : "+f"(c[0]), "+f"(c[1]), "+f"(c[2]), "+f"(c[3])
        : "r"(a0), "r"(a1), "r"(a2), "r"(a3), "r"(b0), "r"(b1));
}
__device__ __forceinline__ uint32_t smem_u32(const void* p) {
    uint32_t a;
    asm("{ .reg .u64 t; cvta.to.shared.u64 t, %1; cvt.u32.u64 %0, t; }"
        : "=r"(a) : "l"(p));
    return a;
}
__device__ __forceinline__ void cp_async16(uint32_t dst, const void* src) {
    asm volatile("cp.async.cg.shared.global [%0], [%1], 16;"
                 :: "r"(dst), "l"(src) : "memory");
}
__device__ __forceinline__ void cp_commit() {
    asm volatile("cp.async.commit_group;" ::: "memory");
}

// ---------------- fp32 -> fp16 convert --------------------------------------
__global__ __launch_bounds__(256) void cvt_h_kernel(
    const float* __restrict__ in, __half* __restrict__ out, int n4)
{
    const int i = blockIdx.x * 256 + threadIdx.x;
    if (i < n4) {
        float4 v = *(const float4*)&in[i * 4];
        __half2 h01 = __floats2half2_rn(v.x, v.y);
        __half2 h23 = __floats2half2_rn(v.z, v.w);
        *(__half2*)&out[i * 4]     = h01;
        *(__half2*)&out[i * 4 + 2] = h23;
    }
}

// ---------------- LayerNorm (fp32 in, fp16 out) ------------------------------
__global__ __launch_bounds__(256) void ln_kernel(
    const float* __restrict__ x, const float* __restrict__ w,
    const float* __restrict__ b, __half* __restrict__ y)
{
    const int row = blockIdx.x;
    const int tid = threadIdx.x;
    const float* xr = x + (size_t)row * D_MODEL;

    float4 v = *(const float4*)&xr[tid * 4];
    float s  = v.x + v.y + v.z + v.w;
    float ss = v.x*v.x + v.y*v.y + v.z*v.z + v.w*v.w;
    #pragma unroll
    for (int o = 16; o > 0; o >>= 1) {
        s  += __shfl_xor_sync(0xffffffffu, s,  o);
        ss += __shfl_xor_sync(0xffffffffu, ss, o);
    }
    __shared__ float rs[8], rss[8];
    if ((tid & 31) == 0) { rs[tid >> 5] = s; rss[tid >> 5] = ss; }
    __syncthreads();
    float ts = 0.f, tss = 0.f;
    #pragma unroll
    for (int i = 0; i < 8; i++) { ts += rs[i]; tss += rss[i]; }

    const float mu  = ts * (1.0f / D_MODEL);
    const float var = fmaxf(tss * (1.0f / D_MODEL) - mu * mu, 0.0f);
    const float inv = rsqrtf(var + 1e-5f);

    float4 wv = *(const float4*)&w[tid * 4];
    float4 bv = *(const float4*)&b[tid * 4];
    __half* yr = y + (size_t)row * D_MODEL + tid * 4;
    *(__half2*)&yr[0] = __floats2half2_rn((v.x - mu) * inv * wv.x + bv.x,
                                          (v.y - mu) * inv * wv.y + bv.y);
    *(__half2*)&yr[2] = __floats2half2_rn((v.z - mu) * inv * wv.z + bv.z,
                                          (v.w - mu) * inv * wv.w + bv.w);
}

// ---------------- fp16 mma.sync GEMM, cp.async 4-stage pipeline -------------
// A[M,K] fp16, B[K,N] fp16 native layout. C = A@B + bias (+ReLU) (+res).
// Output fp32 (Cf) or fp16 (Ch). 128x128 tile, BK=32, 8 warps (2x4), warp 64x32.
#define SA 40      // A_s row stride in halves (80 B)
#define SB 136     // B_s row stride in halves (272 B)
#define ABYTES (128 * SA * 2)          // 10240
#define BBYTES (32 * SB * 2)           // 8704
#define STAGE_BYTES (ABYTES + BBYTES)  // 18944
#define STAGES 4
#define GEMM_SMEM (STAGES * STAGE_BYTES)   // 75776

__device__ __forceinline__ void gemm_load_stage_h(
    const __half* __restrict__ A, const __half* __restrict__ B,
    int N, int K, int bm, int bn, int k0, uint32_t sA, uint32_t sB, int tid)
{
    #pragma unroll
    for (int it = 0; it < 2; it++) {
        const int idx = tid + it * 256;
        const int r = idx >> 2, c16 = idx & 3;
        cp_async16(sA + (uint32_t)(r * 80 + c16 * 16),
                   &A[(size_t)(bm + r) * K + k0 + c16 * 8]);
    }
    #pragma unroll
    for (int it = 0; it < 2; it++) {
        const int idx = tid + it * 256;
        const int k = idx >> 4, c16 = idx & 15;
        cp_async16(sB + (uint32_t)(k * 272 + c16 * 16),
                   &B[(size_t)(k0 + k) * N + bn + c16 * 8]);
    }
}

__global__ __launch_bounds__(256, 2) void gemm_h(
    const __half* __restrict__ A, const __half* __restrict__ B,
    const float* __restrict__ bias, const float* __restrict__ res,
    float* __restrict__ Cf, __half* __restrict__ Ch,
    int M, int N, int K, int relu)
{
    extern __shared__ __align__(16) unsigned short sm_h[];

    const int tid  = threadIdx.x;
    const int wid  = tid >> 5;
    const int lane = tid & 31;
    const int gid  = lane >> 2;
    const int tig  = lane & 3;
    const int wm   = (wid >> 2) * 64;
    const int wn   = (wid & 3) * 32;
    const int bm   = blockIdx.y * 128;
    const int bn   = blockIdx.x * 128;

    const uint32_t smem_base = smem_u32(sm_h);

    float acc[4][4][4];
    #pragma unroll
    for (int mt = 0; mt < 4; mt++)
        #pragma unroll
        for (int nt = 0; nt < 4; nt++)
            #pragma unroll
            for (int r = 0; r < 4; r++) acc[mt][nt][r] = 0.f;

    const int KC = K >> 5;

    // prologue: stages 0..2
    #pragma unroll
    for (int s = 0; s < 3; s++) {
        const uint32_t st = smem_base + (uint32_t)s * STAGE_BYTES;
        gemm_load_stage_h(A, B, N, K, bm, bn, s * 32, st, st + ABYTES, tid);
        cp_commit();
    }

    int stage = 0;
    for (int kc = 0; kc < KC; kc++) {
        if      (kc + 2 < KC) asm volatile("cp.async.wait_group 2;" ::: "memory");
        else if (kc + 1 < KC) asm volatile("cp.async.wait_group 1;" ::: "memory");
        else                  asm volatile("cp.async.wait_group 0;" ::: "memory");
        __syncthreads();

        const unsigned short* Ah = sm_h + stage * (STAGE_BYTES / 2);
        const unsigned short* Bh = Ah + ABYTES / 2;

        #pragma unroll
        for (int ks = 0; ks < 2; ks++) {
            const int kk = ks * 16;
            uint32_t a[4][4];
            #pragma unroll
            for (int mt = 0; mt < 4; mt++) {
                const int base = (wm + mt * 16 + gid) * SA + kk + 2 * tig;
                a[mt][0] = *(const uint32_t*)&Ah[base];
                a[mt][1] = *(const uint32_t*)&Ah[base + 8 * SA];
                a[mt][2] = *(const uint32_t*)&Ah[base + 8];
                a[mt][3] = *(const uint32_t*)&Ah[base + 8 * SA + 8];
            }
            uint32_t bf[4][2];
            #pragma unroll
            for (int nt = 0; nt < 4; nt++) {
                const int n = wn + nt * 8 + gid;
                const int r0 = (kk + 2 * tig) * SB + n;
                uint32_t lo0 = Bh[r0],            hi0 = Bh[r0 + SB];
                uint32_t lo1 = Bh[r0 + 8 * SB],   hi1 = Bh[r0 + 9 * SB];
                bf[nt][0] = lo0 | (hi0 << 16);
                bf[nt][1] = lo1 | (hi1 << 16);
            }
            #pragma unroll
            for (int mt = 0; mt < 4; mt++)
                #pragma unroll
                for (int nt = 0; nt < 4; nt++)
                    mma_f16(acc[mt][nt], a[mt][0], a[mt][1], a[mt][2], a[mt][3],
                            bf[nt][0], bf[nt][1]);
        }

        if (kc + 3 < KC) {
            const int ns = (stage + 3) & 3;
            const uint32_t st = smem_base + (uint32_t)ns * STAGE_BYTES;
            gemm_load_stage_h(A, B, N, K, bm, bn, (kc + 3) * 32,
                              st, st + ABYTES, tid);
            cp_commit();
        } else {
            cp_commit();   // keep group count in lockstep with kc
        }
        stage = (stage + 1) & 3;
    }

    // epilogue
    #pragma unroll
    for (int mt = 0; mt < 4; mt++) {
        #pragma unroll
        for (int r2 = 0; r2 < 2; r2++) {
            const int m = bm + wm + mt * 16 + gid + r2 * 8;
            #pragma unroll
            for (int nt = 0; nt < 4; nt++) {
                const int n = bn + wn + nt * 8 + tig * 2;
                float2 bv = *(const float2*)&bias[n];
                float ox = acc[mt][nt][r2 * 2 + 0] + bv.x;
                float oy = acc[mt][nt][r2 * 2 + 1] + bv.y;
                if (relu) { ox = fmaxf(ox, 0.f); oy = fmaxf(oy, 0.f); }
                if (res) {
                    float2 rv = *(const float2*)&res[(size_t)m * N + n];
                    ox += rv.x; oy += rv.y;
                }
                if (Ch) {
                    *(__half2*)&Ch[(size_t)m * N + n] = __floats2half2_rn(ox, oy);
                } else {
                    float2 o = { ox, oy };
                    *(float2*)&Cf[(size_t)m * N + n] = o;
                }
            }
        }
    }
}

// ---------------- Tensor-core flash attention (tf32, fp32 qkv in, fp16 ctx) -
#define AT_S 72
#define ATTN_SMEM (3 * 64 * AT_S * (int)sizeof(float))

__global__ __launch_bounds__(128, 3) void attn_tc(
    const float* __restrict__ qkv, __half* __restrict__ ctx)
{
    extern __shared__ float sm[];
    uint32_t* Ku = (uint32_t*)sm;
    uint32_t* Vu = Ku + 64 * AT_S;
    uint32_t* Pu = Vu + 64 * AT_S;

    const int qt = blockIdx.x, h = blockIdx.y, b = blockIdx.z;
    const int tid  = threadIdx.x;
    const int w    = tid >> 5;
    const int lane = tid & 31;
    const int gid  = lane >> 2;
    const int tig  = lane & 3;
    const int wm   = w * 16;
    const int q_base = qt * 64;
    const size_t tok0 = (size_t)b * SEQ;
    const float scale = 0.125f;
    const float slope = -exp2f(-(float)h);

    uint32_t qa[8][4];
    {
        const float* q0 = &qkv[(tok0 + q_base + wm + gid    ) * 3072 + h * 64];
        const float* q1 = &qkv[(tok0 + q_base + wm + gid + 8) * 3072 + h * 64];
        #pragma unroll
        for (int ko = 0; ko < 8; ko++) {
            qa[ko][0] = f2tf32(q0[ko * 8 + tig]);
            qa[ko][1] = f2tf32(q1[ko * 8 + tig]);
            qa[ko][2] = f2tf32(q0[ko * 8 + tig + 4]);
            qa[ko][3] = f2tf32(q1[ko * 8 + tig + 4]);
        }
    }

    float m_run[2] = {NEG_BIG, NEG_BIG};
    float l_run[2] = {0.f, 0.f};
    float oa[8][4];
    #pragma unroll
    for (int nt = 0; nt < 8; nt++)
        #pragma unroll
        for (int r = 0; r < 4; r++) oa[nt][r] = 0.f;

    const int i0 = q_base + wm + gid;
    const int i1 = i0 + 8;

    for (int kt = 0; kt <= qt; kt++) {
        const int k_base = kt * 64;
        for (int i = tid; i < 64 * 16; i += 128) {
            const int r = i >> 4, c4 = (i & 15) * 4;
            const float* base = &qkv[(tok0 + k_base + r) * 3072 + h * 64 + c4];
            float4 kv = *(const float4*)(base + 1024);
            float4 vv = *(const float4*)(base + 2048);
            uint4 ku = { f2tf32(kv.x), f2tf32(kv.y), f2tf32(kv.z), f2tf32(kv.w) };
            uint4 vu = { f2tf32(vv.x), f2tf32(vv.y), f2tf32(vv.z), f2tf32(vv.w) };
            *(uint4*)&Ku[r * AT_S + c4] = ku;
            *(uint4*)&Vu[r * AT_S + c4] = vu;
        }
        __syncthreads();

        float sf[8][4];
        #pragma unroll
        for (int nt = 0; nt < 8; nt++)
            #pragma unroll
            for (int r = 0; r < 4; r++) sf[nt][r] = 0.f;
        #pragma unroll
        for (int ko = 0; ko < 8; ko++) {
            const int kk = ko * 8;
            #pragma unroll
            for (int nt = 0; nt < 8; nt++) {
                const uint32_t b0 = Ku[(nt * 8 + gid) * AT_S + kk + tig];
                const uint32_t b1 = Ku[(nt * 8 + gid) * AT_S + kk + tig + 4];
                mma_tf32(sf[nt], qa[ko][0], qa[ko][1], qa[ko][2], qa[ko][3], b0, b1);
            }
        }

        const bool diag = (kt == qt);
        float mx0 = NEG_BIG, mx1 = NEG_BIG;
        #pragma unroll
        for (int nt = 0; nt < 8; nt++) {
            const int j0 = k_base + nt * 8 + tig * 2;
            float v0 = fmaf(sf[nt][0], scale, (float)(i0 + j0    ) * slope);
            float v1 = fmaf(sf[nt][1], scale, (float)(i0 + j0 + 1) * slope);
            float v2 = fmaf(sf[nt][2], scale, (float)(i1 + j0    ) * slope);
            float v3 = fmaf(sf[nt][3], scale, (float)(i1 + j0 + 1) * slope);
            if (diag) {
                if (j0     > i0) v0 = NEG_BIG;
                if (j0 + 1 > i0) v1 = NEG_BIG;
                if (j0     > i1) v2 = NEG_BIG;
                if (j0 + 1 > i1) v3 = NEG_BIG;
            }
            sf[nt][0] = v0; sf[nt][1] = v1; sf[nt][2] = v2; sf[nt][3] = v3;
            mx0 = fmaxf(mx0, fmaxf(v0, v1));
            mx1 = fmaxf(mx1, fmaxf(v2, v3));
        }
        mx0 = fmaxf(mx0, __shfl_xor_sync(0xffffffffu, mx0, 1));
        mx0 = fmaxf(mx0, __shfl_xor_sync(0xffffffffu, mx0, 2));
        mx1 = fmaxf(mx1, __shfl_xor_sync(0xffffffffu, mx1, 1));
        mx1 = fmaxf(mx1, __shfl_xor_sync(0xffffffffu, mx1, 2));

        const float mn0 = fmaxf(m_run[0], mx0);
        const float mn1 = fmaxf(m_run[1], mx1);
        const float corr0 = __expf(m_run[0] - mn0);
        const float corr1 = __expf(m_run[1] - mn1);
        float s0 = 0.f, s1 = 0.f;
        #pragma unroll
        for (int nt = 0; nt < 8; nt++) {
            const float p0 = __expf(sf[nt][0] - mn0);
            const float p1 = __expf(sf[nt][1] - mn0);
            const float p2 = __expf(sf[nt][2] - mn1);
            const float p3 = __expf(sf[nt][3] - mn1);
            s0 += p0 + p1; s1 += p2 + p3;
            uint32_t* p0p = &Pu[(wm + gid    ) * AT_S + nt * 8 + tig * 2];
            uint32_t* p1p = &Pu[(wm + gid + 8) * AT_S + nt * 8 + tig * 2];
            p0p[0] = f2tf32(p0); p0p[1] = f2tf32(p1);
            p1p[0] = f2tf32(p2); p1p[1] = f2tf32(p3);
        }
        s0 += __shfl_xor_sync(0xffffffffu, s0, 1);
        s0 += __shfl_xor_sync(0xffffffffu, s0, 2);
        s1 += __shfl_xor_sync(0xffffffffu, s1, 1);
        s1 += __shfl_xor_sync(0xffffffffu, s1, 2);
        l_run[0] = l_run[0] * corr0 + s0;
        l_run[1] = l_run[1] * corr1 + s1;
        m_run[0] = mn0; m_run[1] = mn1;
        #pragma unroll
        for (int nt = 0; nt < 8; nt++) {
            oa[nt][0] *= corr0; oa[nt][1] *= corr0;
            oa[nt][2] *= corr1; oa[nt][3] *= corr1;
        }
        __syncthreads();

        #pragma unroll
        for (int ko = 0; ko < 8; ko++) {
            const int kk = ko * 8;
            uint32_t a0 = Pu[(wm + gid    ) * AT_S + kk + tig];
            uint32_t a1 = Pu[(wm + gid + 8) * AT_S + kk + tig];
            uint32_t a2 = Pu[(wm + gid    ) * AT_S + kk + tig + 4];
            uint32_t a3 = Pu[(wm + gid + 8) * AT_S + kk + tig + 4];
            #pragma unroll
            for (int nt = 0; nt < 8; nt++) {
                const uint32_t b0 = Vu[(kk + tig    ) * AT_S + nt * 8 + gid];
                const uint32_t b1 = Vu[(kk + tig + 4) * AT_S + nt * 8 + gid];
                mma_tf32(oa[nt], a0, a1, a2, a3, b0, b1);
            }
        }
        __syncthreads();
    }

    const float inv0 = 1.0f / l_run[0];
    const float inv1 = 1.0f / l_run[1];
    __half* c0 = &ctx[(tok0 + q_base + wm + gid    ) * D_MODEL + h * 64];
    __half* c1 = &ctx[(tok0 + q_base + wm + gid + 8) * D_MODEL + h * 64];
    #pragma unroll
    for (int nt = 0; nt < 8; nt++) {
        *(__half2*)&c0[nt * 8 + tig * 2] =
            __floats2half2_rn(oa[nt][0] * inv0, oa[nt][1] * inv0);
        *(__half2*)&c1[nt * 8 + tig * 2] =
            __floats2half2_rn(oa[nt][2] * inv1, oa[nt][3] * inv1);
    }
}

// ---------------- launch ----------------------------------------------------
extern "C" void kernel_launch(void* const* d_in, const int* in_sizes, int n_in,
                              void* d_out, int out_size)
{
    const float* src  = (const float*)d_in[0];
    const float* ln1w = (const float*)d_in[1];
    const float* ln1b = (const float*)d_in[2];
    const float* wqkv = (const float*)d_in[3];
    const float* bqkv = (const float*)d_in[4];
    const float* wo   = (const float*)d_in[5];
    const float* bo   = (const float*)d_in[6];
    const float* ln2w = (const float*)d_in[7];
    const float* ln2b = (const float*)d_in[8];
    const float* w1   = (const float*)d_in[9];
    const float* b1   = (const float*)d_in[10];
    const float* w2   = (const float*)d_in[11];
    const float* b2   = (const float*)d_in[12];
    float* out = (float*)d_out;

    __half *xn, *ctx, *ff1, *wqkvh, *woh, *w1h, *w2h;
    float *qkv, *src2;
    cudaGetSymbolAddress((void**)&xn,    g_xn_h);
    cudaGetSymbolAddress((void**)&qkv,   g_qkv);
    cudaGetSymbolAddress((void**)&ctx,   g_ctx_h);
    cudaGetSymbolAddress((void**)&src2,  g_src2);
    cudaGetSymbolAddress((void**)&ff1,   g_ff1_h);
    cudaGetSymbolAddress((void**)&wqkvh, g_wqkv_h);
    cudaGetSymbolAddress((void**)&woh,   g_wo_h);
    cudaGetSymbolAddress((void**)&w1h,   g_w1_h);
    cudaGetSymbolAddress((void**)&w2h,   g_w2_h);

    cudaFuncSetAttribute(attn_tc,
                         cudaFuncAttributeMaxDynamicSharedMemorySize, ATTN_SMEM);
    cudaFuncSetAttribute(gemm_h,
                         cudaFuncAttributeMaxDynamicSharedMemorySize, GEMM_SMEM);

    // weight conversions fp32->fp16
    cvt_h_kernel<<<(3 * D_MODEL * D_MODEL / 4 + 255) / 256, 256>>>(
        wqkv, wqkvh, 3 * D_MODEL * D_MODEL / 4);
    cvt_h_kernel<<<(D_MODEL * D_MODEL / 4 + 255) / 256, 256>>>(
        wo, woh, D_MODEL * D_MODEL / 4);
    cvt_h_kernel<<<(D_MODEL * DFF / 4 + 255) / 256, 256>>>(
        w1, w1h, D_MODEL * DFF / 4);
    cvt_h_kernel<<<(DFF * D_MODEL / 4 + 255) / 256, 256>>>(
        w2, w2h, DFF * D_MODEL / 4);

    // 1) LN1 -> fp16
    ln_kernel<<<NTOK, 256>>>(src, ln1w, ln1b, xn);
    // 2) QKV projection (fp16 in, fp32 out for attention)
    gemm_h<<<dim3(3 * D_MODEL / 128, NTOK / 128), 256, GEMM_SMEM>>>(
        xn, wqkvh, bqkv, nullptr, qkv, nullptr, NTOK, 3 * D_MODEL, D_MODEL, 0);
    // 3) attention -> fp16 ctx
    attn_tc<<<dim3(SEQ / 64, NH, BATCH), 128, ATTN_SMEM>>>(qkv, ctx);
    // 4) output projection + residual -> fp32 src2
    gemm_h<<<dim3(D_MODEL / 128, NTOK / 128), 256, GEMM_SMEM>>>(
        ctx, woh, bo, src, src2, nullptr, NTOK, D_MODEL, D_MODEL, 0);
    // 5) LN2 -> fp16
    ln_kernel<<<NTOK, 256>>>(src2, ln2w, ln2b, xn);
    // 6) FFN up + ReLU -> fp16 ff1
    gemm_h<<<dim3(DFF / 128, NTOK / 128), 256, GEMM_SMEM>>>(
        xn, w1h, b1, nullptr, nullptr, ff1, NTOK, DFF, D_MODEL, 1);
    // 7) FFN down + residual -> fp32 out
    gemm_h<<<dim3(D_MODEL / 128, NTOK / 128), 256, GEMM_SMEM>>>(
        ff1, w2h, b2, src2, out, nullptr, NTOK, D_MODEL, DFF, 0);
}

// round 6
// speedup vs baseline: 6.8775x; 1.3953x over previous
#include <cuda_runtime.h>
#include <cuda_fp16.h>
#include <cstdint>
#include <math.h>

#define D_MODEL 1024
#define NH      16
#define DFF     4096
#define SEQ     2048
#define BATCH   2
#define NTOK    (BATCH*SEQ)          // 4096
#define NEG_BIG (-1e30f)

// ---------------- scratch (allocation-free rule: __device__ globals) --------
__device__ __half g_xn_h [NTOK * D_MODEL];
__device__ __half g_qkv_h[NTOK * 3 * D_MODEL];
__device__ __half g_ctx_h[NTOK * D_MODEL];
__device__ float  g_src2 [NTOK * D_MODEL];
__device__ __half g_ff1_h[NTOK * DFF];
__device__ __half g_wqkv_h[D_MODEL * 3 * D_MODEL];
__device__ __half g_wo_h  [D_MODEL * D_MODEL];
__device__ __half g_w1_h  [D_MODEL * DFF];
__device__ __half g_w2_h  [DFF * D_MODEL];

// ---------------- helpers ----------------------------------------------------
__device__ __forceinline__ void mma_f16(float c[4], uint32_t a0, uint32_t a1,
                                        uint32_t a2, uint32_t a3,
                                        uint32_t b0, uint32_t b1) {
    asm volatile(
        "mma.sync.aligned.m16n8k16.row.col.f32.f16.f16.f32 "
        "{%0,%1,%2,%3}, {%4,%5,%6,%7}, {%8,%9}, {%0,%1,%2,%3};"
        : "+f"(c[0]), "+f"(c[1]), "+f"(c[2]), "+f"(c[3])
        : "r"(a0), "r"(a1), "r"(a2), "r"(a3), "r"(b0), "r"(b1));
}
__device__ __forceinline__ void ldmx4(uint32_t& r0, uint32_t& r1,
                                      uint32_t& r2, uint32_t& r3, uint32_t addr) {
    asm volatile("ldmatrix.sync.aligned.m8n8.x4.shared.b16 {%0,%1,%2,%3}, [%4];"
                 : "=r"(r0), "=r"(r1), "=r"(r2), "=r"(r3) : "r"(addr));
}
__device__ __forceinline__ void ldmx4t(uint32_t& r0, uint32_t& r1,
                                       uint32_t& r2, uint32_t& r3, uint32_t addr) {
    asm volatile("ldmatrix.sync.aligned.m8n8.x4.trans.shared.b16 {%0,%1,%2,%3}, [%4];"
                 : "=r"(r0), "=r"(r1), "=r"(r2), "=r"(r3) : "r"(addr));
}
__device__ __forceinline__ uint32_t smem_u32(const void* p) {
    uint32_t a;
    asm("{ .reg .u64 t; cvta.to.shared.u64 t, %1; cvt.u32.u64 %0, t; }"
        : "=r"(a) : "l"(p));
    return a;
}
__device__ __forceinline__ void cp_async16(uint32_t dst, const void* src) {
    asm volatile("cp.async.cg.shared.global [%0], [%1], 16;"
                 :: "r"(dst), "l"(src) : "memory");
}
__device__ __forceinline__ void cp_commit() {
    asm volatile("cp.async.commit_group;" ::: "memory");
}
__device__ __forceinline__ uint32_t h2bits(float a, float b) {
    __half2 h = __floats2half2_rn(a, b);
    return *(uint32_t*)&h;
}

// ---------------- fp32 -> fp16 convert --------------------------------------
__global__ __launch_bounds__(256) void cvt_h_kernel(
    const float* __restrict__ in, __half* __restrict__ out, int n4)
{
    const int i = blockIdx.x * 256 + threadIdx.x;
    if (i < n4) {
        float4 v = *(const float4*)&in[i * 4];
        *(__half2*)&out[i * 4]     = __floats2half2_rn(v.x, v.y);
        *(__half2*)&out[i * 4 + 2] = __floats2half2_rn(v.z, v.w);
    }
}

// ---------------- LayerNorm (fp32 in, fp16 out) ------------------------------
__global__ __launch_bounds__(256) void ln_kernel(
    const float* __restrict__ x, const float* __restrict__ w,
    const float* __restrict__ b, __half* __restrict__ y)
{
    const int row = blockIdx.x;
    const int tid = threadIdx.x;
    const float* xr = x + (size_t)row * D_MODEL;

    float4 v = *(const float4*)&xr[tid * 4];
    float s  = v.x + v.y + v.z + v.w;
    float ss = v.x*v.x + v.y*v.y + v.z*v.z + v.w*v.w;
    #pragma unroll
    for (int o = 16; o > 0; o >>= 1) {
        s  += __shfl_xor_sync(0xffffffffu, s,  o);
        ss += __shfl_xor_sync(0xffffffffu, ss, o);
    }
    __shared__ float rs[8], rss[8];
    if ((tid & 31) == 0) { rs[tid >> 5] = s; rss[tid >> 5] = ss; }
    __syncthreads();
    float ts = 0.f, tss = 0.f;
    #pragma unroll
    for (int i = 0; i < 8; i++) { ts += rs[i]; tss += rss[i]; }

    const float mu  = ts * (1.0f / D_MODEL);
    const float var = fmaxf(tss * (1.0f / D_MODEL) - mu * mu, 0.0f);
    const float inv = rsqrtf(var + 1e-5f);

    float4 wv = *(const float4*)&w[tid * 4];
    float4 bv = *(const float4*)&b[tid * 4];
    __half* yr = y + (size_t)row * D_MODEL + tid * 4;
    *(__half2*)&yr[0] = __floats2half2_rn((v.x - mu) * inv * wv.x + bv.x,
                                          (v.y - mu) * inv * wv.y + bv.y);
    *(__half2*)&yr[2] = __floats2half2_rn((v.z - mu) * inv * wv.z + bv.z,
                                          (v.w - mu) * inv * wv.w + bv.w);
}

// ---------------- fp16 mma.sync GEMM, cp.async 4-stage, ldmatrix frags ------
#define SA 40      // A_s row stride in halves (80 B)
#define SB 136     // B_s row stride in halves (272 B)
#define ABYTES (128 * SA * 2)          // 10240
#define BBYTES (32 * SB * 2)           // 8704
#define STAGE_BYTES (ABYTES + BBYTES)  // 18944
#define STAGES 4
#define GEMM_SMEM (STAGES * STAGE_BYTES)   // 75776

__device__ __forceinline__ void gemm_load_stage_h(
    const __half* __restrict__ A, const __half* __restrict__ B,
    int N, int K, int bm, int bn, int k0, uint32_t sA, uint32_t sB, int tid)
{
    #pragma unroll
    for (int it = 0; it < 2; it++) {
        const int idx = tid + it * 256;
        const int r = idx >> 2, c16 = idx & 3;
        cp_async16(sA + (uint32_t)(r * 80 + c16 * 16),
                   &A[(size_t)(bm + r) * K + k0 + c16 * 8]);
    }
    #pragma unroll
    for (int it = 0; it < 2; it++) {
        const int idx = tid + it * 256;
        const int k = idx >> 4, c16 = idx & 15;
        cp_async16(sB + (uint32_t)(k * 272 + c16 * 16),
                   &B[(size_t)(k0 + k) * N + bn + c16 * 8]);
    }
}

__global__ __launch_bounds__(256, 2) void gemm_h(
    const __half* __restrict__ A, const __half* __restrict__ B,
    const float* __restrict__ bias, const float* __restrict__ res,
    float* __restrict__ Cf, __half* __restrict__ Ch,
    int M, int N, int K, int relu)
{
    extern __shared__ __align__(16) unsigned short sm_h[];

    const int tid  = threadIdx.x;
    const int wid  = tid >> 5;
    const int lane = tid & 31;
    const int gid  = lane >> 2;
    const int tig  = lane & 3;
    const int wm   = (wid >> 2) * 64;
    const int wn   = (wid & 3) * 32;
    const int bm   = blockIdx.y * 128;
    const int bn   = blockIdx.x * 128;

    const uint32_t smem_base = smem_u32(sm_h);

    float acc[4][4][4];
    #pragma unroll
    for (int mt = 0; mt < 4; mt++)
        #pragma unroll
        for (int nt = 0; nt < 4; nt++)
            #pragma unroll
            for (int r = 0; r < 4; r++) acc[mt][nt][r] = 0.f;

    const int KC = K >> 5;

    #pragma unroll
    for (int s = 0; s < 3; s++) {
        const uint32_t st = smem_base + (uint32_t)s * STAGE_BYTES;
        gemm_load_stage_h(A, B, N, K, bm, bn, s * 32, st, st + ABYTES, tid);
        cp_commit();
    }

    // per-thread ldmatrix address components
    const int a_row = lane & 15;            // row within 16-row block
    const int a_col8 = 8 * (lane >> 4);     // +8 col for upper 16 lanes
    const int b_krow = (lane & 7) + 8 * ((lane >> 3) & 1);
    const int b_col8 = 8 * (lane >> 4);

    int stage = 0;
    for (int kc = 0; kc < KC; kc++) {
        if      (kc + 2 < KC) asm volatile("cp.async.wait_group 2;" ::: "memory");
        else if (kc + 1 < KC) asm volatile("cp.async.wait_group 1;" ::: "memory");
        else                  asm volatile("cp.async.wait_group 0;" ::: "memory");
        __syncthreads();

        const uint32_t aBase = smem_base + (uint32_t)stage * STAGE_BYTES;
        const uint32_t bBase = aBase + ABYTES;

        #pragma unroll
        for (int ks = 0; ks < 2; ks++) {
            const int kk = ks * 16;
            uint32_t a[4][4];
            #pragma unroll
            for (int mt = 0; mt < 4; mt++)
                ldmx4(a[mt][0], a[mt][1], a[mt][2], a[mt][3],
                      aBase + (uint32_t)(((wm + mt * 16 + a_row) * SA
                                          + kk + a_col8) * 2));
            uint32_t bf[4][2];
            #pragma unroll
            for (int np = 0; np < 2; np++) {
                uint32_t r0, r1, r2, r3;
                ldmx4t(r0, r1, r2, r3,
                       bBase + (uint32_t)(((kk + b_krow) * SB
                                           + wn + np * 16 + b_col8) * 2));
                bf[np * 2][0] = r0;     bf[np * 2][1] = r1;
                bf[np * 2 + 1][0] = r2; bf[np * 2 + 1][1] = r3;
            }
            #pragma unroll
            for (int mt = 0; mt < 4; mt++)
                #pragma unroll
                for (int nt = 0; nt < 4; nt++)
                    mma_f16(acc[mt][nt], a[mt][0], a[mt][1], a[mt][2], a[mt][3],
                            bf[nt][0], bf[nt][1]);
        }

        if (kc + 3 < KC) {
            const int ns = (stage + 3) & 3;
            const uint32_t st = smem_base + (uint32_t)ns * STAGE_BYTES;
            gemm_load_stage_h(A, B, N, K, bm, bn, (kc + 3) * 32,
                              st, st + ABYTES, tid);
            cp_commit();
        } else {
            cp_commit();
        }
        stage = (stage + 1) & 3;
    }

    #pragma unroll
    for (int mt = 0; mt < 4; mt++) {
        #pragma unroll
        for (int r2 = 0; r2 < 2; r2++) {
            const int m = bm + wm + mt * 16 + gid + r2 * 8;
            #pragma unroll
            for (int nt = 0; nt < 4; nt++) {
                const int n = bn + wn + nt * 8 + tig * 2;
                float2 bv = *(const float2*)&bias[n];
                float ox = acc[mt][nt][r2 * 2 + 0] + bv.x;
                float oy = acc[mt][nt][r2 * 2 + 1] + bv.y;
                if (relu) { ox = fmaxf(ox, 0.f); oy = fmaxf(oy, 0.f); }
                if (res) {
                    float2 rv = *(const float2*)&res[(size_t)m * N + n];
                    ox += rv.x; oy += rv.y;
                }
                if (Ch) {
                    *(__half2*)&Ch[(size_t)m * N + n] = __floats2half2_rn(ox, oy);
                } else {
                    float2 o = { ox, oy };
                    *(float2*)&Cf[(size_t)m * N + n] = o;
                }
            }
        }
    }
}

// ---------------- fp16 tensor-core flash attention (ALiBi + causal) ---------
// Block: 64 q-rows x (head, batch). 128 threads, warp owns 16 rows.
// K/V tiles fp16 in smem; Q and P fragments live in registers.
#define SK 72   // smem row stride in halves

__global__ __launch_bounds__(128) void attn_h(
    const __half* __restrict__ qkv, __half* __restrict__ ctx)
{
    __shared__ __align__(16) __half Kh[64 * SK];
    __shared__ __align__(16) __half Vh[64 * SK];

    const int qt = blockIdx.x, h = blockIdx.y, b = blockIdx.z;
    const int tid  = threadIdx.x;
    const int w    = tid >> 5;
    const int lane = tid & 31;
    const int gid  = lane >> 2;
    const int tig  = lane & 3;
    const int wm   = w * 16;
    const int q_base = qt * 64;
    const size_t tok0 = (size_t)b * SEQ;
    const float scale = 0.125f;
    const float slope = -exp2f(-(float)h);

    const uint32_t kBase = smem_u32(Kh);
    const uint32_t vBase = smem_u32(Vh);

    // Q fragments (fp16) in registers
    uint32_t qa[4][4];
    {
        const __half* q0 = &qkv[(tok0 + q_base + wm + gid    ) * 3072 + h * 64];
        const __half* q1 = &qkv[(tok0 + q_base + wm + gid + 8) * 3072 + h * 64];
        #pragma unroll
        for (int ko = 0; ko < 4; ko++) {
            qa[ko][0] = *(const uint32_t*)&q0[ko * 16 + 2 * tig];
            qa[ko][1] = *(const uint32_t*)&q1[ko * 16 + 2 * tig];
            qa[ko][2] = *(const uint32_t*)&q0[ko * 16 + 8 + 2 * tig];
            qa[ko][3] = *(const uint32_t*)&q1[ko * 16 + 8 + 2 * tig];
        }
    }

    float m_run[2] = {NEG_BIG, NEG_BIG};
    float l_run[2] = {0.f, 0.f};
    float oa[8][4];
    #pragma unroll
    for (int nt = 0; nt < 8; nt++)
        #pragma unroll
        for (int r = 0; r < 4; r++) oa[nt][r] = 0.f;

    const int i0 = q_base + wm + gid;
    const int i1 = i0 + 8;

    // ldmatrix lane components
    const int m_row  = lane & 15;
    const int m_col8 = 8 * (lane >> 4);
    const int t_krow = (lane & 7) + 8 * ((lane >> 3) & 1);

    for (int kt = 0; kt <= qt; kt++) {
        const int k_base = kt * 64;
        // load K,V (fp16, 16B vectors)
        for (int i = tid; i < 512; i += 128) {
            const int r = i >> 3, c8 = (i & 7) * 8;
            const __half* kb = &qkv[(tok0 + k_base + r) * 3072 + 1024 + h * 64 + c8];
            *(uint4*)&Kh[r * SK + c8] = *(const uint4*)kb;
            *(uint4*)&Vh[r * SK + c8] = *(const uint4*)(kb + 1024);
        }
        __syncthreads();

        // S = Q K^T
        float sf[8][4];
        #pragma unroll
        for (int nt = 0; nt < 8; nt++)
            #pragma unroll
            for (int r = 0; r < 4; r++) sf[nt][r] = 0.f;
        #pragma unroll
        for (int ko = 0; ko < 4; ko++) {
            #pragma unroll
            for (int nb = 0; nb < 4; nb++) {
                uint32_t r0, r1, r2, r3;
                ldmx4(r0, r1, r2, r3,
                      kBase + (uint32_t)(((nb * 16 + m_row) * SK
                                          + ko * 16 + m_col8) * 2));
                mma_f16(sf[2 * nb    ], qa[ko][0], qa[ko][1], qa[ko][2], qa[ko][3], r0, r2);
                mma_f16(sf[2 * nb + 1], qa[ko][0], qa[ko][1], qa[ko][2], qa[ko][3], r1, r3);
            }
        }

        // softmax over this 64-key tile
        const bool diag = (kt == qt);
        float mx0 = NEG_BIG, mx1 = NEG_BIG;
        #pragma unroll
        for (int nt = 0; nt < 8; nt++) {
            const int j0 = k_base + nt * 8 + tig * 2;
            float v0 = fmaf(sf[nt][0], scale, (float)(i0 + j0    ) * slope);
            float v1 = fmaf(sf[nt][1], scale, (float)(i0 + j0 + 1) * slope);
            float v2 = fmaf(sf[nt][2], scale, (float)(i1 + j0    ) * slope);
            float v3 = fmaf(sf[nt][3], scale, (float)(i1 + j0 + 1) * slope);
            if (diag) {
                if (j0     > i0) v0 = NEG_BIG;
                if (j0 + 1 > i0) v1 = NEG_BIG;
                if (j0     > i1) v2 = NEG_BIG;
                if (j0 + 1 > i1) v3 = NEG_BIG;
            }
            sf[nt][0] = v0; sf[nt][1] = v1; sf[nt][2] = v2; sf[nt][3] = v3;
            mx0 = fmaxf(mx0, fmaxf(v0, v1));
            mx1 = fmaxf(mx1, fmaxf(v2, v3));
        }
        mx0 = fmaxf(mx0, __shfl_xor_sync(0xffffffffu, mx0, 1));
        mx0 = fmaxf(mx0, __shfl_xor_sync(0xffffffffu, mx0, 2));
        mx1 = fmaxf(mx1, __shfl_xor_sync(0xffffffffu, mx1, 1));
        mx1 = fmaxf(mx1, __shfl_xor_sync(0xffffffffu, mx1, 2));

        const float mn0 = fmaxf(m_run[0], mx0);
        const float mn1 = fmaxf(m_run[1], mx1);
        const float corr0 = __expf(m_run[0] - mn0);
        const float corr1 = __expf(m_run[1] - mn1);
        float s0 = 0.f, s1 = 0.f;
        uint32_t pH[8][2];
        #pragma unroll
        for (int nt = 0; nt < 8; nt++) {
            const float p0 = __expf(sf[nt][0] - mn0);
            const float p1 = __expf(sf[nt][1] - mn0);
            const float p2 = __expf(sf[nt][2] - mn1);
            const float p3 = __expf(sf[nt][3] - mn1);
            s0 += p0 + p1; s1 += p2 + p3;
            pH[nt][0] = h2bits(p0, p1);
            pH[nt][1] = h2bits(p2, p3);
        }
        s0 += __shfl_xor_sync(0xffffffffu, s0, 1);
        s0 += __shfl_xor_sync(0xffffffffu, s0, 2);
        s1 += __shfl_xor_sync(0xffffffffu, s1, 1);
        s1 += __shfl_xor_sync(0xffffffffu, s1, 2);
        l_run[0] = l_run[0] * corr0 + s0;
        l_run[1] = l_run[1] * corr1 + s1;
        m_run[0] = mn0; m_run[1] = mn1;
        #pragma unroll
        for (int nt = 0; nt < 8; nt++) {
            oa[nt][0] *= corr0; oa[nt][1] *= corr0;
            oa[nt][2] *= corr1; oa[nt][3] *= corr1;
        }

        // O += P V  (P fragments straight from registers)
        #pragma unroll
        for (int ko2 = 0; ko2 < 4; ko2++) {
            const uint32_t pa0 = pH[2 * ko2][0];
            const uint32_t pa1 = pH[2 * ko2][1];
            const uint32_t pa2 = pH[2 * ko2 + 1][0];
            const uint32_t pa3 = pH[2 * ko2 + 1][1];
            #pragma unroll
            for (int vb = 0; vb < 4; vb++) {
                uint32_t r0, r1, r2, r3;
                ldmx4t(r0, r1, r2, r3,
                       vBase + (uint32_t)(((ko2 * 16 + t_krow) * SK
                                           + vb * 16 + 8 * (lane >> 4)) * 2));
                mma_f16(oa[2 * vb    ], pa0, pa1, pa2, pa3, r0, r1);
                mma_f16(oa[2 * vb + 1], pa0, pa1, pa2, pa3, r2, r3);
            }
        }
        __syncthreads();
    }

    const float inv0 = 1.0f / l_run[0];
    const float inv1 = 1.0f / l_run[1];
    __half* c0 = &ctx[(tok0 + q_base + wm + gid    ) * D_MODEL + h * 64];
    __half* c1 = &ctx[(tok0 + q_base + wm + gid + 8) * D_MODEL + h * 64];
    #pragma unroll
    for (int nt = 0; nt < 8; nt++) {
        *(__half2*)&c0[nt * 8 + tig * 2] =
            __floats2half2_rn(oa[nt][0] * inv0, oa[nt][1] * inv0);
        *(__half2*)&c1[nt * 8 + tig * 2] =
            __floats2half2_rn(oa[nt][2] * inv1, oa[nt][3] * inv1);
    }
}

// ---------------- launch ----------------------------------------------------
extern "C" void kernel_launch(void* const* d_in, const int* in_sizes, int n_in,
                              void* d_out, int out_size)
{
    const float* src  = (const float*)d_in[0];
    const float* ln1w = (const float*)d_in[1];
    const float* ln1b = (const float*)d_in[2];
    const float* wqkv = (const float*)d_in[3];
    const float* bqkv = (const float*)d_in[4];
    const float* wo   = (const float*)d_in[5];
    const float* bo   = (const float*)d_in[6];
    const float* ln2w = (const float*)d_in[7];
    const float* ln2b = (const float*)d_in[8];
    const float* w1   = (const float*)d_in[9];
    const float* b1   = (const float*)d_in[10];
    const float* w2   = (const float*)d_in[11];
    const float* b2   = (const float*)d_in[12];
    float* out = (float*)d_out;

    __half *xn, *qkvh, *ctx, *ff1, *wqkvh, *woh, *w1h, *w2h;
    float *src2;
    cudaGetSymbolAddress((void**)&xn,    g_xn_h);
    cudaGetSymbolAddress((void**)&qkvh,  g_qkv_h);
    cudaGetSymbolAddress((void**)&ctx,   g_ctx_h);
    cudaGetSymbolAddress((void**)&src2,  g_src2);
    cudaGetSymbolAddress((void**)&ff1,   g_ff1_h);
    cudaGetSymbolAddress((void**)&wqkvh, g_wqkv_h);
    cudaGetSymbolAddress((void**)&woh,   g_wo_h);
    cudaGetSymbolAddress((void**)&w1h,   g_w1_h);
    cudaGetSymbolAddress((void**)&w2h,   g_w2_h);

    cudaFuncSetAttribute(gemm_h,
                         cudaFuncAttributeMaxDynamicSharedMemorySize, GEMM_SMEM);

    // weight conversions fp32->fp16
    cvt_h_kernel<<<(3 * D_MODEL * D_MODEL / 4 + 255) / 256, 256>>>(
        wqkv, wqkvh, 3 * D_MODEL * D_MODEL / 4);
    cvt_h_kernel<<<(D_MODEL * D_MODEL / 4 + 255) / 256, 256>>>(
        wo, woh, D_MODEL * D_MODEL / 4);
    cvt_h_kernel<<<(D_MODEL * DFF / 4 + 255) / 256, 256>>>(
        w1, w1h, D_MODEL * DFF / 4);
    cvt_h_kernel<<<(DFF * D_MODEL / 4 + 255) / 256, 256>>>(
        w2, w2h, DFF * D_MODEL / 4);

    // 1) LN1 -> fp16
    ln_kernel<<<NTOK, 256>>>(src, ln1w, ln1b, xn);
    // 2) QKV projection -> fp16 qkv
    gemm_h<<<dim3(3 * D_MODEL / 128, NTOK / 128), 256, GEMM_SMEM>>>(
        xn, wqkvh, bqkv, nullptr, nullptr, qkvh, NTOK, 3 * D_MODEL, D_MODEL, 0);
    // 3) attention (fp16) -> fp16 ctx
    attn_h<<<dim3(SEQ / 64, NH, BATCH), 128>>>(qkvh, ctx);
    // 4) output projection + residual -> fp32 src2
    gemm_h<<<dim3(D_MODEL / 128, NTOK / 128), 256, GEMM_SMEM>>>(
        ctx, woh, bo, src, src2, nullptr, NTOK, D_MODEL, D_MODEL, 0);
    // 5) LN2 -> fp16
    ln_kernel<<<NTOK, 256>>>(src2, ln2w, ln2b, xn);
    // 6) FFN up + ReLU -> fp16 ff1
    gemm_h<<<dim3(DFF / 128, NTOK / 128), 256, GEMM_SMEM>>>(
        xn, w1h, b1, nullptr, nullptr, ff1, NTOK, DFF, D_MODEL, 1);
    // 7) FFN down + residual -> fp32 out
    gemm_h<<<dim3(D_MODEL / 128, NTOK / 128), 256, GEMM_SMEM>>>(
        ff1, w2h, b2, src2, out, nullptr, NTOK, D_MODEL, DFF, 0);
}